// round 5
// baseline (speedup 1.0000x reference)
#include <cuda_runtime.h>
#include <cuda_bf16.h>
#include <math.h>
#include <stdint.h>

#define NB 512
#define NT 256
#define NC 384
#define NH 64
#define NS 256
#define NM (NB*NT)   // 131072 rows

// scratch (device globals: allocation-guard safe)
__device__ __align__(16) __nv_bfloat16 g_vh[NM * 64];    // v split hi [row][64]
__device__ __align__(16) __nv_bfloat16 g_vl[NM * 64];    // v split lo
__device__ __align__(16) __nv_bfloat16 g_wvh[64 * 384];  // Wv [n][k] K-major split
__device__ __align__(16) __nv_bfloat16 g_wvl[64 * 384];
__device__ __align__(16) __nv_bfloat16 g_wuh[384 * 256]; // Wu = Wq@Wql + Wk@Wkl, [k][s] split
__device__ __align__(16) __nv_bfloat16 g_wul[384 * 256];

// ---------------- mma.sync helpers (baseline PTX ISA) ----------------
#define LDSM_X4(r, addr)                                                        \
    asm volatile("ldmatrix.sync.aligned.m8n8.x4.shared.b16 {%0,%1,%2,%3}, [%4];" \
        : "=r"((r)[0]), "=r"((r)[1]), "=r"((r)[2]), "=r"((r)[3]) : "r"(addr))

#define LDSM_X4_T(r, addr)                                                      \
    asm volatile("ldmatrix.sync.aligned.m8n8.x4.trans.shared.b16 {%0,%1,%2,%3}, [%4];" \
        : "=r"((r)[0]), "=r"((r)[1]), "=r"((r)[2]), "=r"((r)[3]) : "r"(addr))

#define MMA_BF16(d, a, b)                                                       \
    asm volatile("mma.sync.aligned.m16n8k16.row.col.f32.bf16.bf16.f32 "         \
        "{%0,%1,%2,%3}, {%4,%5,%6,%7}, {%8,%9}, {%0,%1,%2,%3};"                 \
        : "+f"((d)[0]), "+f"((d)[1]), "+f"((d)[2]), "+f"((d)[3])                \
        : "r"((a)[0]), "r"((a)[1]), "r"((a)[2]), "r"((a)[3]),                   \
          "r"((b)[0]), "r"((b)[1]))

static __device__ __forceinline__ uint32_t pack_bf2(float a, float b) {
    __nv_bfloat162 t = __floats2bfloat162_rn(a, b);
    return *(uint32_t*)&t;
}
static __device__ __forceinline__ uint32_t smaddr(const void* p) {
    return (uint32_t)__cvta_generic_to_shared(p);
}

// ---------------- Wu = Wq@Wql + Wk@Wkl  (fp32, then split) ----------------
__global__ __launch_bounds__(256) void wu_kernel(
    const float* __restrict__ Wq, const float* __restrict__ Wk,
    const float* __restrict__ Wql, const float* __restrict__ Wkl)
{
    __shared__ float qr_[64], kr_[64];
    const int c = blockIdx.x;      // 0..383
    const int s = threadIdx.x;     // 0..255
    if (s < 64)       qr_[s]      = Wq[c * 64 + s];
    else if (s < 128) kr_[s - 64] = Wk[c * 64 + s - 64];
    __syncthreads();
    float acc = 0.f;
#pragma unroll 8
    for (int h = 0; h < 64; h++)
        acc = fmaf(qr_[h], Wql[h * 256 + s], fmaf(kr_[h], Wkl[h * 256 + s], acc));
    __nv_bfloat16 hh = __float2bfloat16(acc);
    g_wuh[c * 256 + s] = hh;
    g_wul[c * 256 + s] = __float2bfloat16(acc - __bfloat162float(hh));
}

// ---------------- Wv split (K-major) ----------------
__global__ __launch_bounds__(256) void convert_wv_kernel(const float* __restrict__ Wv)
{
    const int idx = blockIdx.x * 256 + threadIdx.x;
    if (idx >= 64 * 384) return;
    const int n = idx / 384, k = idx % 384;
    float v = Wv[k * 64 + n];
    __nv_bfloat16 h = __float2bfloat16(v);
    g_wvh[idx] = h;
    g_wvl[idx] = __float2bfloat16(v - __bfloat162float(h));
}

// ---------------- Kernel A: v projection, split-bf16 output ----------------
// CTA: 256 rows x 64 cols; 8 warps = 4m(64 rows) x 2n(32 cols); K=384 in 32-chunks.
#define VPROJ_SMEM ((256*40 + 256*40 + 64*40 + 64*40) * 2)

__global__ __launch_bounds__(256) void vproj_kernel(const float* __restrict__ x)
{
    extern __shared__ __nv_bfloat16 smv[];
    __nv_bfloat16* sXH = smv;               // [256][40]
    __nv_bfloat16* sXL = sXH + 256 * 40;
    __nv_bfloat16* sWH = sXL + 256 * 40;    // [64][40]
    __nv_bfloat16* sWL = sWH + 64 * 40;

    const int tid  = threadIdx.x;
    const int lane = tid & 31;
    const int w    = tid >> 5;
    const int wm   = w & 3;       // rows wm*64
    const int wn   = w >> 2;      // cols wn*32
    const int m0   = blockIdx.x * 256;

    const int a_row = (lane & 7) + ((lane >> 3) & 1) * 8;
    const int a_col = (lane >> 4) * 8;
    const int b_row = ((lane >> 4) * 8) + (lane & 7);   // x4 pair: lanes>=16 -> tile+1
    const int b_k8  = ((lane >> 3) & 1) * 8;
    const int qr    = lane >> 2;
    const int qc    = (lane & 3) * 2;

    float acc[4][4][4];
#pragma unroll
    for (int mi = 0; mi < 4; mi++)
#pragma unroll
        for (int ni = 0; ni < 4; ni++)
#pragma unroll
            for (int q = 0; q < 4; q++) acc[mi][ni][q] = 0.f;

    for (int c = 0; c < 12; c++) {
        const int kc = c * 32;
        __syncthreads();
        // stage x: 256 rows x 32 cols, split inline
#pragma unroll
        for (int i = 0; i < 8; i++) {
            int idx = tid + 256 * i;
            int row = idx >> 3, seg = idx & 7;
            float4 v = *(const float4*)&x[(size_t)(m0 + row) * NC + kc + seg * 4];
            float vv[4] = {v.x, v.y, v.z, v.w};
            __nv_bfloat16 h[4], l[4];
#pragma unroll
            for (int j = 0; j < 4; j++) {
                h[j] = __float2bfloat16(vv[j]);
                l[j] = __float2bfloat16(vv[j] - __bfloat162float(h[j]));
            }
            *(uint2*)&sXH[row * 40 + seg * 4] = *(uint2*)h;
            *(uint2*)&sXL[row * 40 + seg * 4] = *(uint2*)l;
        }
        // stage Wv chunk: 64 rows x 32 k
        {
            int row = tid >> 2, seg = tid & 3;
            *(uint4*)&sWH[row * 40 + seg * 8] =
                *(const uint4*)&g_wvh[(size_t)row * NC + kc + seg * 8];
            *(uint4*)&sWL[row * 40 + seg * 8] =
                *(const uint4*)&g_wvl[(size_t)row * NC + kc + seg * 8];
        }
        __syncthreads();

#pragma unroll
        for (int kk = 0; kk < 2; kk++) {
            const int k0 = kk * 16;
            uint32_t ah[4][4], al[4][4];
#pragma unroll
            for (int mi = 0; mi < 4; mi++) {
                LDSM_X4(ah[mi], smaddr(&sXH[(wm * 64 + mi * 16 + a_row) * 40 + k0 + a_col]));
                LDSM_X4(al[mi], smaddr(&sXL[(wm * 64 + mi * 16 + a_row) * 40 + k0 + a_col]));
            }
#pragma unroll
            for (int ni = 0; ni < 4; ni += 2) {
                uint32_t bh[4], bl[4];
                LDSM_X4(bh, smaddr(&sWH[(wn * 32 + ni * 8 + b_row) * 40 + k0 + b_k8]));
                LDSM_X4(bl, smaddr(&sWL[(wn * 32 + ni * 8 + b_row) * 40 + k0 + b_k8]));
#pragma unroll
                for (int mi = 0; mi < 4; mi++) {
                    MMA_BF16(acc[mi][ni],     ah[mi], bh);
                    MMA_BF16(acc[mi][ni],     al[mi], bh);
                    MMA_BF16(acc[mi][ni],     ah[mi], bl);
                    MMA_BF16(acc[mi][ni + 1], ah[mi], bh + 2);
                    MMA_BF16(acc[mi][ni + 1], al[mi], bh + 2);
                    MMA_BF16(acc[mi][ni + 1], ah[mi], bl + 2);
                }
            }
        }
    }

    // epilogue: split-bf16 store to g_vh/g_vl
#pragma unroll
    for (int mi = 0; mi < 4; mi++) {
        int r0 = m0 + wm * 64 + mi * 16 + qr;
#pragma unroll
        for (int ni = 0; ni < 4; ni++) {
            int col = wn * 32 + ni * 8 + qc;
            uint32_t h01 = pack_bf2(acc[mi][ni][0], acc[mi][ni][1]);
            uint32_t h23 = pack_bf2(acc[mi][ni][2], acc[mi][ni][3]);
            __nv_bfloat162 t0 = *(__nv_bfloat162*)&h01;
            __nv_bfloat162 t1 = *(__nv_bfloat162*)&h23;
            uint32_t l01 = pack_bf2(acc[mi][ni][0] - __low2float(t0),
                                    acc[mi][ni][1] - __high2float(t0));
            uint32_t l23 = pack_bf2(acc[mi][ni][2] - __low2float(t1),
                                    acc[mi][ni][3] - __high2float(t1));
            *(uint32_t*)&g_vh[(size_t)r0 * 64 + col]       = h01;
            *(uint32_t*)&g_vl[(size_t)r0 * 64 + col]       = l01;
            *(uint32_t*)&g_vh[(size_t)(r0 + 8) * 64 + col] = h23;
            *(uint32_t*)&g_vl[(size_t)(r0 + 8) * 64 + col] = l23;
        }
    }
}

// ---------------- Kernel B: fused u-GEMM + softmax + p@v ----------------
// Per block (b,tb): u[64][SLIM] = x[64][384] @ Wu[384][SLIM] (split-bf16 3-term),
// p = exp(tanh(u)) masked, row-normalized; out = p @ v (v pre-split).
// 8 warps: 4 in m (16 rows) x 2 in n/k halves.

template <int SLIM>
__device__ __forceinline__ void attn_body(const float* __restrict__ x,
                                          float* __restrict__ out, int b, int tb)
{
    constexpr int SLIMP = SLIM + 8;
    constexpr int NTW   = SLIM / 16;   // n8 tiles per warp
    constexpr int KW    = SLIM / 2;

    extern __shared__ char smraw[];
    __nv_bfloat16* sVH = (__nv_bfloat16*)smraw;          // [SLIM][72]
    __nv_bfloat16* sVL = sVH + SLIM * 72;
    __nv_bfloat16* sXH = sVL + SLIM * 72;                // [2][64][40]
    __nv_bfloat16* sXL = sXH + 2 * 64 * 40;
    __nv_bfloat16* sWH = sXL + 2 * 64 * 40;              // [2][32][SLIMP]
    __nv_bfloat16* sWL = sWH + 2 * 32 * SLIMP;
    float* rowsumS     = (float*)(sWL + 2 * 32 * SLIMP); // [2][64]
    float* sOut        = (float*)sWH;                    // reuse after GEMM1

    const int tid  = threadIdx.x;
    const int lane = tid & 31;
    const int w    = tid >> 5;
    const int wm   = w >> 1;
    const int wn   = w & 1;

    const int a_row  = (lane & 7) + ((lane >> 3) & 1) * 8;
    const int a_col  = (lane >> 4) * 8;
    const int kt_off = (lane & 7) | (((lane >> 3) & 1) << 3);  // x4.trans k-row
    const int nt_off = (lane >> 4) * 8;                        // x4.trans n pair
    const int qr     = lane >> 2;
    const int qc     = (lane & 3) * 2;
    const int base_row = b * NT + tb * 64;

    // stage v (pre-split bf16)
    for (int L = tid; L < SLIM * 8; L += 256) {
        int s = L >> 3, seg = L & 7;
        *(uint4*)&sVH[s * 72 + seg * 8] = *(const uint4*)&g_vh[(size_t)(b * NT + s) * 64 + seg * 8];
        *(uint4*)&sVL[s * 72 + seg * 8] = *(const uint4*)&g_vl[(size_t)(b * NT + s) * 64 + seg * 8];
    }

    auto stageX = [&](int c, int buf) {
        const int kc = c * 32;
#pragma unroll
        for (int i = 0; i < 2; i++) {
            int idx = tid + 256 * i;
            int row = idx >> 3, seg = idx & 7;
            float4 v = *(const float4*)&x[(size_t)(base_row + row) * NC + kc + seg * 4];
            float vv[4] = {v.x, v.y, v.z, v.w};
            __nv_bfloat16 h[4], l[4];
#pragma unroll
            for (int j = 0; j < 4; j++) {
                h[j] = __float2bfloat16(vv[j]);
                l[j] = __float2bfloat16(vv[j] - __bfloat162float(h[j]));
            }
            *(uint2*)&sXH[buf * 2560 + row * 40 + seg * 4] = *(uint2*)h;
            *(uint2*)&sXL[buf * 2560 + row * 40 + seg * 4] = *(uint2*)l;
        }
    };
    auto stageW = [&](int c, int buf) {
        const int kc = c * 32;
        for (int L = tid; L < 4 * SLIM; L += 256) {
            int r = L / (SLIM / 8), cs = L % (SLIM / 8);
            *(uint4*)&sWH[(buf * 32 + r) * SLIMP + cs * 8] =
                *(const uint4*)&g_wuh[(size_t)(kc + r) * 256 + cs * 8];
            *(uint4*)&sWL[(buf * 32 + r) * SLIMP + cs * 8] =
                *(const uint4*)&g_wul[(size_t)(kc + r) * 256 + cs * 8];
        }
    };

    stageX(0, 0);
    stageW(0, 0);
    __syncthreads();

    // ---- GEMM1: K=384 in 12 chunks, double buffered ----
    float acc[NTW][4];
#pragma unroll
    for (int j = 0; j < NTW; j++)
#pragma unroll
        for (int q = 0; q < 4; q++) acc[j][q] = 0.f;

    for (int c = 0; c < 12; c++) {
        const int buf = c & 1;
        if (c < 11) { stageX(c + 1, buf ^ 1); stageW(c + 1, buf ^ 1); }
#pragma unroll
        for (int kk = 0; kk < 2; kk++) {
            uint32_t ah[4], al[4];
            LDSM_X4(ah, smaddr(&sXH[buf * 2560 + (wm * 16 + a_row) * 40 + kk * 16 + a_col]));
            LDSM_X4(al, smaddr(&sXL[buf * 2560 + (wm * 16 + a_row) * 40 + kk * 16 + a_col]));
#pragma unroll
            for (int j = 0; j < NTW; j += 2) {
                uint32_t bh[4], bl[4];
                const int n0 = wn * KW + j * 8 + nt_off;
                LDSM_X4_T(bh, smaddr(&sWH[(buf * 32 + kk * 16 + kt_off) * SLIMP + n0]));
                LDSM_X4_T(bl, smaddr(&sWL[(buf * 32 + kk * 16 + kt_off) * SLIMP + n0]));
                MMA_BF16(acc[j],     ah, bh);
                MMA_BF16(acc[j],     al, bh);
                MMA_BF16(acc[j],     ah, bl);
                MMA_BF16(acc[j + 1], ah, bh + 2);
                MMA_BF16(acc[j + 1], al, bh + 2);
                MMA_BF16(acc[j + 1], ah, bl + 2);
            }
        }
        __syncthreads();
    }

    // ---- tanh + causal mask + exp + row sums (tanh bounded: no max pass) ----
    const int tg0 = tb * 64 + wm * 16 + qr;
    float rsum0 = 0.f, rsum1 = 0.f;
#pragma unroll
    for (int j = 0; j < NTW; j++) {
        const int c0 = wn * KW + j * 8 + qc;
        float v0 = (c0     <= tg0    ) ? __expf(tanhf(acc[j][0])) : 0.f;
        float v1 = (c0 + 1 <= tg0    ) ? __expf(tanhf(acc[j][1])) : 0.f;
        float v2 = (c0     <= tg0 + 8) ? __expf(tanhf(acc[j][2])) : 0.f;
        float v3 = (c0 + 1 <= tg0 + 8) ? __expf(tanhf(acc[j][3])) : 0.f;
        acc[j][0] = v0; acc[j][1] = v1; acc[j][2] = v2; acc[j][3] = v3;
        rsum0 += v0 + v1;
        rsum1 += v2 + v3;
    }
#pragma unroll
    for (int off = 1; off <= 2; off <<= 1) {
        rsum0 += __shfl_xor_sync(0xffffffffu, rsum0, off);
        rsum1 += __shfl_xor_sync(0xffffffffu, rsum1, off);
    }
    if ((lane & 3) == 0) {
        rowsumS[wn * 64 + wm * 16 + qr]     = rsum0;
        rowsumS[wn * 64 + wm * 16 + qr + 8] = rsum1;
    }
    __syncthreads();
    const float inv0 = 1.f / (rowsumS[wm * 16 + qr]     + rowsumS[64 + wm * 16 + qr]);
    const float inv1 = 1.f / (rowsumS[wm * 16 + qr + 8] + rowsumS[64 + wm * 16 + qr + 8]);

    // ---- GEMM2: out += p @ v over k in [wn*KW, wn*KW+KW) ----
    float acc2[8][4];
#pragma unroll
    for (int jo = 0; jo < 8; jo++)
#pragma unroll
        for (int q = 0; q < 4; q++) acc2[jo][q] = 0.f;

#pragma unroll
    for (int jp = 0; jp < NTW / 2; jp++) {
        float c00 = acc[2*jp][0]   * inv0, c01 = acc[2*jp][1]   * inv0;
        float c02 = acc[2*jp][2]   * inv1, c03 = acc[2*jp][3]   * inv1;
        float c10 = acc[2*jp+1][0] * inv0, c11 = acc[2*jp+1][1] * inv0;
        float c12 = acc[2*jp+1][2] * inv1, c13 = acc[2*jp+1][3] * inv1;

        uint32_t pa_h[4], pa_l[4];
        pa_h[0] = pack_bf2(c00, c01);
        pa_h[1] = pack_bf2(c02, c03);
        pa_h[2] = pack_bf2(c10, c11);
        pa_h[3] = pack_bf2(c12, c13);
        {
            __nv_bfloat162 t0 = *(__nv_bfloat162*)&pa_h[0];
            __nv_bfloat162 t1 = *(__nv_bfloat162*)&pa_h[1];
            __nv_bfloat162 t2 = *(__nv_bfloat162*)&pa_h[2];
            __nv_bfloat162 t3 = *(__nv_bfloat162*)&pa_h[3];
            pa_l[0] = pack_bf2(c00 - __low2float(t0), c01 - __high2float(t0));
            pa_l[1] = pack_bf2(c02 - __low2float(t1), c03 - __high2float(t1));
            pa_l[2] = pack_bf2(c10 - __low2float(t2), c11 - __high2float(t2));
            pa_l[3] = pack_bf2(c12 - __low2float(t3), c13 - __high2float(t3));
        }

        const int k0 = wn * KW + jp * 16;
#pragma unroll
        for (int jo = 0; jo < 8; jo += 2) {
            uint32_t bh[4], bl[4];
            LDSM_X4_T(bh, smaddr(&sVH[(k0 + kt_off) * 72 + jo * 8 + nt_off]));
            LDSM_X4_T(bl, smaddr(&sVL[(k0 + kt_off) * 72 + jo * 8 + nt_off]));
            MMA_BF16(acc2[jo],     pa_h, bh);
            MMA_BF16(acc2[jo],     pa_l, bh);
            MMA_BF16(acc2[jo],     pa_h, bl);
            MMA_BF16(acc2[jo + 1], pa_h, bh + 2);
            MMA_BF16(acc2[jo + 1], pa_l, bh + 2);
            MMA_BF16(acc2[jo + 1], pa_h, bl + 2);
        }
    }

    // ---- cross-warp k-reduction + store ----
    __syncthreads();
    if (wn == 0) {
#pragma unroll
        for (int jo = 0; jo < 8; jo++) {
            *(float2*)&sOut[(wm * 16 + qr)     * 72 + jo * 8 + qc] =
                make_float2(acc2[jo][0], acc2[jo][1]);
            *(float2*)&sOut[(wm * 16 + qr + 8) * 72 + jo * 8 + qc] =
                make_float2(acc2[jo][2], acc2[jo][3]);
        }
    }
    __syncthreads();
    if (wn == 1) {
        const int trow0 = base_row + wm * 16 + qr;
#pragma unroll
        for (int jo = 0; jo < 8; jo++) {
            float2 p0 = *(float2*)&sOut[(wm * 16 + qr)     * 72 + jo * 8 + qc];
            float2 p1 = *(float2*)&sOut[(wm * 16 + qr + 8) * 72 + jo * 8 + qc];
            *(float2*)&out[(size_t)trow0 * NH + jo * 8 + qc] =
                make_float2(acc2[jo][0] + p0.x, acc2[jo][1] + p0.y);
            *(float2*)&out[(size_t)(trow0 + 8) * NH + jo * 8 + qc] =
                make_float2(acc2[jo][2] + p1.x, acc2[jo][3] + p1.y);
        }
    }
}

__global__ __launch_bounds__(256) void attn_kernel(const float* __restrict__ x,
                                                   float* __restrict__ out)
{
    const int tb = blockIdx.x;
    const int b  = blockIdx.y;
    if (tb == 0)      attn_body<64 >(x, out, b, 0);
    else if (tb == 1) attn_body<128>(x, out, b, 1);
    else if (tb == 2) attn_body<192>(x, out, b, 2);
    else              attn_body<256>(x, out, b, 3);
}

// SLIM=256: v 2*256*72*2 + x 2*2*64*40*2 + w 2*2*32*264*2 + 512 = 162304
#define ATTN_SMEM_BYTES 162304

extern "C" void kernel_launch(void* const* d_in, const int* in_sizes, int n_in,
                              void* d_out, int out_size)
{
    (void)in_sizes; (void)n_in; (void)out_size;
    const float* x   = (const float*)d_in[0];
    const float* Wq  = (const float*)d_in[1];
    const float* Wk  = (const float*)d_in[2];
    const float* Wv  = (const float*)d_in[3];
    const float* Wql = (const float*)d_in[4];
    const float* Wkl = (const float*)d_in[5];
    float* out = (float*)d_out;

    cudaFuncSetAttribute((const void*)attn_kernel,
                         cudaFuncAttributeMaxDynamicSharedMemorySize, ATTN_SMEM_BYTES);
    cudaFuncSetAttribute((const void*)vproj_kernel,
                         cudaFuncAttributeMaxDynamicSharedMemorySize, VPROJ_SMEM);

    convert_wv_kernel<<<(64 * 384 + 255) / 256, 256>>>(Wv);
    wu_kernel<<<384, 256>>>(Wq, Wk, Wql, Wkl);
    vproj_kernel<<<NM / 256, 256, VPROJ_SMEM>>>(x);

    dim3 grid(4, NB);
    attn_kernel<<<grid, 256, ATTN_SMEM_BYTES>>>(x, out);
}

// round 6
// speedup vs baseline: 1.6463x; 1.6463x over previous
#include <cuda_runtime.h>
#include <cuda_bf16.h>
#include <math.h>
#include <stdint.h>

#define NB 512
#define NT 256
#define NC 384
#define NH 64
#define NS 256
#define NM (NB*NT)   // 131072 rows

// scratch (device globals: allocation-guard safe)
__device__ __align__(16) __nv_bfloat16 g_vh[NM * 64];    // v split hi [row][64]
__device__ __align__(16) __nv_bfloat16 g_vl[NM * 64];    // v split lo
__device__ __align__(16) __nv_bfloat16 g_wvh[64 * 384];  // Wv [n][k] K-major split
__device__ __align__(16) __nv_bfloat16 g_wvl[64 * 384];
__device__ __align__(16) __nv_bfloat16 g_wuh[384 * 256]; // Wu = Wq@Wql + Wk@Wkl, [k][s] split
__device__ __align__(16) __nv_bfloat16 g_wul[384 * 256];

// ---------------- mma.sync / cp.async helpers (baseline PTX ISA) ----------------
#define LDSM_X4(r, addr)                                                        \
    asm volatile("ldmatrix.sync.aligned.m8n8.x4.shared.b16 {%0,%1,%2,%3}, [%4];" \
        : "=r"((r)[0]), "=r"((r)[1]), "=r"((r)[2]), "=r"((r)[3]) : "r"(addr))

#define LDSM_X4_T(r, addr)                                                      \
    asm volatile("ldmatrix.sync.aligned.m8n8.x4.trans.shared.b16 {%0,%1,%2,%3}, [%4];" \
        : "=r"((r)[0]), "=r"((r)[1]), "=r"((r)[2]), "=r"((r)[3]) : "r"(addr))

#define MMA_BF16(d, a, b)                                                       \
    asm volatile("mma.sync.aligned.m16n8k16.row.col.f32.bf16.bf16.f32 "         \
        "{%0,%1,%2,%3}, {%4,%5,%6,%7}, {%8,%9}, {%0,%1,%2,%3};"                 \
        : "+f"((d)[0]), "+f"((d)[1]), "+f"((d)[2]), "+f"((d)[3])                \
        : "r"((a)[0]), "r"((a)[1]), "r"((a)[2]), "r"((a)[3]),                   \
          "r"((b)[0]), "r"((b)[1]))

#define CP_ASYNC16(dst, src)                                                    \
    asm volatile("cp.async.cg.shared.global [%0], [%1], 16;"                    \
        :: "r"(dst), "l"(src))
#define CP_COMMIT  asm volatile("cp.async.commit_group;" ::: "memory")
#define CP_WAIT0   asm volatile("cp.async.wait_group 0;" ::: "memory")

static __device__ __forceinline__ uint32_t pack_bf2(float a, float b) {
    __nv_bfloat162 t = __floats2bfloat162_rn(a, b);
    return *(uint32_t*)&t;
}
static __device__ __forceinline__ uint32_t smaddr(const void* p) {
    return (uint32_t)__cvta_generic_to_shared(p);
}

// ---------------- Wu = Wq@Wql + Wk@Wkl  (fp32, then split) ----------------
__global__ __launch_bounds__(256) void wu_kernel(
    const float* __restrict__ Wq, const float* __restrict__ Wk,
    const float* __restrict__ Wql, const float* __restrict__ Wkl)
{
    __shared__ float qr_[64], kr_[64];
    const int c = blockIdx.x;
    const int s = threadIdx.x;
    if (s < 64)       qr_[s]      = Wq[c * 64 + s];
    else if (s < 128) kr_[s - 64] = Wk[c * 64 + s - 64];
    __syncthreads();
    float acc = 0.f;
#pragma unroll 8
    for (int h = 0; h < 64; h++)
        acc = fmaf(qr_[h], Wql[h * 256 + s], fmaf(kr_[h], Wkl[h * 256 + s], acc));
    __nv_bfloat16 hh = __float2bfloat16(acc);
    g_wuh[c * 256 + s] = hh;
    g_wul[c * 256 + s] = __float2bfloat16(acc - __bfloat162float(hh));
}

// ---------------- Wv split (K-major) ----------------
__global__ __launch_bounds__(256) void convert_wv_kernel(const float* __restrict__ Wv)
{
    const int idx = blockIdx.x * 256 + threadIdx.x;
    if (idx >= 64 * 384) return;
    const int n = idx / 384, k = idx % 384;
    float v = Wv[k * 64 + n];
    __nv_bfloat16 h = __float2bfloat16(v);
    g_wvh[idx] = h;
    g_wvl[idx] = __float2bfloat16(v - __bfloat162float(h));
}

// ---------------- Kernel A: v projection, split-bf16 output ----------------
#define VPROJ_SMEM ((256*40 + 256*40 + 64*40 + 64*40) * 2)

__global__ __launch_bounds__(256) void vproj_kernel(const float* __restrict__ x)
{
    extern __shared__ __nv_bfloat16 smv[];
    __nv_bfloat16* sXH = smv;               // [256][40]
    __nv_bfloat16* sXL = sXH + 256 * 40;
    __nv_bfloat16* sWH = sXL + 256 * 40;    // [64][40]
    __nv_bfloat16* sWL = sWH + 64 * 40;

    const int tid  = threadIdx.x;
    const int lane = tid & 31;
    const int w    = tid >> 5;
    const int wm   = w & 3;
    const int wn   = w >> 2;
    const int m0   = blockIdx.x * 256;

    const int a_row = (lane & 7) + ((lane >> 3) & 1) * 8;
    const int a_col = (lane >> 4) * 8;
    const int b_row = ((lane >> 4) * 8) + (lane & 7);
    const int b_k8  = ((lane >> 3) & 1) * 8;
    const int qr    = lane >> 2;
    const int qc    = (lane & 3) * 2;

    float acc[4][4][4];
#pragma unroll
    for (int mi = 0; mi < 4; mi++)
#pragma unroll
        for (int ni = 0; ni < 4; ni++)
#pragma unroll
            for (int q = 0; q < 4; q++) acc[mi][ni][q] = 0.f;

    for (int c = 0; c < 12; c++) {
        const int kc = c * 32;
        __syncthreads();
#pragma unroll
        for (int i = 0; i < 8; i++) {
            int idx = tid + 256 * i;
            int row = idx >> 3, seg = idx & 7;
            float4 v = *(const float4*)&x[(size_t)(m0 + row) * NC + kc + seg * 4];
            float vv[4] = {v.x, v.y, v.z, v.w};
            __nv_bfloat16 h[4], l[4];
#pragma unroll
            for (int j = 0; j < 4; j++) {
                h[j] = __float2bfloat16(vv[j]);
                l[j] = __float2bfloat16(vv[j] - __bfloat162float(h[j]));
            }
            *(uint2*)&sXH[row * 40 + seg * 4] = *(uint2*)h;
            *(uint2*)&sXL[row * 40 + seg * 4] = *(uint2*)l;
        }
        {
            int row = tid >> 2, seg = tid & 3;
            *(uint4*)&sWH[row * 40 + seg * 8] =
                *(const uint4*)&g_wvh[(size_t)row * NC + kc + seg * 8];
            *(uint4*)&sWL[row * 40 + seg * 8] =
                *(const uint4*)&g_wvl[(size_t)row * NC + kc + seg * 8];
        }
        __syncthreads();

#pragma unroll
        for (int kk = 0; kk < 2; kk++) {
            const int k0 = kk * 16;
            uint32_t ah[4][4], al[4][4];
#pragma unroll
            for (int mi = 0; mi < 4; mi++) {
                LDSM_X4(ah[mi], smaddr(&sXH[(wm * 64 + mi * 16 + a_row) * 40 + k0 + a_col]));
                LDSM_X4(al[mi], smaddr(&sXL[(wm * 64 + mi * 16 + a_row) * 40 + k0 + a_col]));
            }
#pragma unroll
            for (int ni = 0; ni < 4; ni += 2) {
                uint32_t bh[4], bl[4];
                LDSM_X4(bh, smaddr(&sWH[(wn * 32 + ni * 8 + b_row) * 40 + k0 + b_k8]));
                LDSM_X4(bl, smaddr(&sWL[(wn * 32 + ni * 8 + b_row) * 40 + k0 + b_k8]));
#pragma unroll
                for (int mi = 0; mi < 4; mi++) {
                    MMA_BF16(acc[mi][ni],     ah[mi], bh);
                    MMA_BF16(acc[mi][ni],     al[mi], bh);
                    MMA_BF16(acc[mi][ni],     ah[mi], bl);
                    MMA_BF16(acc[mi][ni + 1], ah[mi], bh + 2);
                    MMA_BF16(acc[mi][ni + 1], al[mi], bh + 2);
                    MMA_BF16(acc[mi][ni + 1], ah[mi], bl + 2);
                }
            }
        }
    }

#pragma unroll
    for (int mi = 0; mi < 4; mi++) {
        int r0 = m0 + wm * 64 + mi * 16 + qr;
#pragma unroll
        for (int ni = 0; ni < 4; ni++) {
            int col = wn * 32 + ni * 8 + qc;
            uint32_t h01 = pack_bf2(acc[mi][ni][0], acc[mi][ni][1]);
            uint32_t h23 = pack_bf2(acc[mi][ni][2], acc[mi][ni][3]);
            __nv_bfloat162 t0 = *(__nv_bfloat162*)&h01;
            __nv_bfloat162 t1 = *(__nv_bfloat162*)&h23;
            uint32_t l01 = pack_bf2(acc[mi][ni][0] - __low2float(t0),
                                    acc[mi][ni][1] - __high2float(t0));
            uint32_t l23 = pack_bf2(acc[mi][ni][2] - __low2float(t1),
                                    acc[mi][ni][3] - __high2float(t1));
            *(uint32_t*)&g_vh[(size_t)r0 * 64 + col]       = h01;
            *(uint32_t*)&g_vl[(size_t)r0 * 64 + col]       = l01;
            *(uint32_t*)&g_vh[(size_t)(r0 + 8) * 64 + col] = h23;
            *(uint32_t*)&g_vl[(size_t)(r0 + 8) * 64 + col] = l23;
        }
    }
}

// ---------------- Kernel B: fused u-GEMM + softmax + p@v ----------------
// smem phase overlay: phase1 x+W buffers (88.1KB); phase2 v (73.7KB) in same region.
// rowsum lives at fixed tail offset. 88.6KB total -> 2 CTAs/SM.
#define ATTN_SMEM_BYTES 88576

template <int SLIM>
__device__ __forceinline__ void attn_body(const float* __restrict__ x,
                                          float* __restrict__ out, int b, int tb)
{
    constexpr int SLIMP = SLIM + 8;
    constexpr int NTW   = SLIM / 16;
    constexpr int KW    = SLIM / 2;

    extern __shared__ char smraw[];
    // phase 1
    __nv_bfloat16* sXH = (__nv_bfloat16*)smraw;          // [2][64][40]
    __nv_bfloat16* sXL = sXH + 2 * 64 * 40;
    __nv_bfloat16* sWH = sXL + 2 * 64 * 40;              // [2][32][SLIMP]
    __nv_bfloat16* sWL = sWH + 2 * 32 * SLIMP;
    // phase 2 (overlays phase 1)
    __nv_bfloat16* sVH = (__nv_bfloat16*)smraw;          // [SLIM][72]
    __nv_bfloat16* sVL = sVH + SLIM * 72;
    float* sOut        = (float*)smraw;                  // [64][72], after v dead
    float* rowsumS     = (float*)(smraw + 88064);        // [2][64]

    const int tid  = threadIdx.x;
    const int lane = tid & 31;
    const int w    = tid >> 5;
    const int wm   = w >> 1;
    const int wn   = w & 1;

    const int a_row  = (lane & 7) + ((lane >> 3) & 1) * 8;
    const int a_col  = (lane >> 4) * 8;
    const int kt_off = (lane & 7) | (((lane >> 3) & 1) << 3);
    const int nt_off = (lane >> 4) * 8;
    const int qr     = lane >> 2;
    const int qc     = (lane & 3) * 2;
    const int base_row = b * NT + tb * 64;

    auto stageX = [&](int c, int buf) {
        const int kc = c * 32;
#pragma unroll
        for (int i = 0; i < 2; i++) {
            int idx = tid + 256 * i;
            int row = idx >> 3, seg = idx & 7;
            float4 v = *(const float4*)&x[(size_t)(base_row + row) * NC + kc + seg * 4];
            float vv[4] = {v.x, v.y, v.z, v.w};
            __nv_bfloat16 h[4], l[4];
#pragma unroll
            for (int j = 0; j < 4; j++) {
                h[j] = __float2bfloat16(vv[j]);
                l[j] = __float2bfloat16(vv[j] - __bfloat162float(h[j]));
            }
            *(uint2*)&sXH[buf * 2560 + row * 40 + seg * 4] = *(uint2*)h;
            *(uint2*)&sXL[buf * 2560 + row * 40 + seg * 4] = *(uint2*)l;
        }
    };
    auto stageW = [&](int c, int buf) {     // cp.async: pure bf16 16B copies
        const int kc = c * 32;
        for (int L = tid; L < 4 * SLIM; L += 256) {
            int r = L / (SLIM / 8), cs = L % (SLIM / 8);
            CP_ASYNC16(smaddr(&sWH[(buf * 32 + r) * SLIMP + cs * 8]),
                       &g_wuh[(size_t)(kc + r) * 256 + cs * 8]);
            CP_ASYNC16(smaddr(&sWL[(buf * 32 + r) * SLIMP + cs * 8]),
                       &g_wul[(size_t)(kc + r) * 256 + cs * 8]);
        }
    };

    stageW(0, 0);
    CP_COMMIT;
    stageX(0, 0);
    CP_WAIT0;
    __syncthreads();

    // ---- GEMM1: u = x @ Wu, K=384 in 12 chunks, double buffered ----
    float acc[NTW][4];
#pragma unroll
    for (int j = 0; j < NTW; j++)
#pragma unroll
        for (int q = 0; q < 4; q++) acc[j][q] = 0.f;

    for (int c = 0; c < 12; c++) {
        const int buf = c & 1;
        if (c < 11) {
            stageW(c + 1, buf ^ 1);
            CP_COMMIT;
            stageX(c + 1, buf ^ 1);
        }
#pragma unroll
        for (int kk = 0; kk < 2; kk++) {
            uint32_t ah[4], al[4];
            LDSM_X4(ah, smaddr(&sXH[buf * 2560 + (wm * 16 + a_row) * 40 + kk * 16 + a_col]));
            LDSM_X4(al, smaddr(&sXL[buf * 2560 + (wm * 16 + a_row) * 40 + kk * 16 + a_col]));
#pragma unroll
            for (int j = 0; j < NTW; j += 2) {
                uint32_t bh[4], bl[4];
                const int n0 = wn * KW + j * 8 + nt_off;
                LDSM_X4_T(bh, smaddr(&sWH[(buf * 32 + kk * 16 + kt_off) * SLIMP + n0]));
                LDSM_X4_T(bl, smaddr(&sWL[(buf * 32 + kk * 16 + kt_off) * SLIMP + n0]));
                MMA_BF16(acc[j],     ah, bh);
                MMA_BF16(acc[j],     al, bh);
                MMA_BF16(acc[j],     ah, bl);
                MMA_BF16(acc[j + 1], ah, bh + 2);
                MMA_BF16(acc[j + 1], al, bh + 2);
                MMA_BF16(acc[j + 1], ah, bl + 2);
            }
        }
        if (c < 11) CP_WAIT0;
        __syncthreads();
    }

    // ---- v staging into (dead) phase-1 region, overlapped with softmax ----
    for (int L = tid; L < SLIM * 8; L += 256) {
        int s = L >> 3, seg = L & 7;
        CP_ASYNC16(smaddr(&sVH[s * 72 + seg * 8]),
                   &g_vh[(size_t)(b * NT + s) * 64 + seg * 8]);
        CP_ASYNC16(smaddr(&sVL[s * 72 + seg * 8]),
                   &g_vl[(size_t)(b * NT + s) * 64 + seg * 8]);
    }
    CP_COMMIT;

    // ---- tanh + causal mask + exp + row sums (tanh bounded: no max pass) ----
    const int tg0 = tb * 64 + wm * 16 + qr;
    float rsum0 = 0.f, rsum1 = 0.f;
#pragma unroll
    for (int j = 0; j < NTW; j++) {
        const int c0 = wn * KW + j * 8 + qc;
        float v0 = (c0     <= tg0    ) ? __expf(tanhf(acc[j][0])) : 0.f;
        float v1 = (c0 + 1 <= tg0    ) ? __expf(tanhf(acc[j][1])) : 0.f;
        float v2 = (c0     <= tg0 + 8) ? __expf(tanhf(acc[j][2])) : 0.f;
        float v3 = (c0 + 1 <= tg0 + 8) ? __expf(tanhf(acc[j][3])) : 0.f;
        acc[j][0] = v0; acc[j][1] = v1; acc[j][2] = v2; acc[j][3] = v3;
        rsum0 += v0 + v1;
        rsum1 += v2 + v3;
    }
#pragma unroll
    for (int off = 1; off <= 2; off <<= 1) {
        rsum0 += __shfl_xor_sync(0xffffffffu, rsum0, off);
        rsum1 += __shfl_xor_sync(0xffffffffu, rsum1, off);
    }
    if ((lane & 3) == 0) {
        rowsumS[wn * 64 + wm * 16 + qr]     = rsum0;
        rowsumS[wn * 64 + wm * 16 + qr + 8] = rsum1;
    }
    __syncthreads();
    const float inv0 = 1.f / (rowsumS[wm * 16 + qr]     + rowsumS[64 + wm * 16 + qr]);
    const float inv1 = 1.f / (rowsumS[wm * 16 + qr + 8] + rowsumS[64 + wm * 16 + qr + 8]);

    CP_WAIT0;          // own v copies done
    __syncthreads();   // everyone's v copies done

    // ---- GEMM2: out += p @ v over k in [wn*KW, wn*KW+KW) ----
    float acc2[8][4];
#pragma unroll
    for (int jo = 0; jo < 8; jo++)
#pragma unroll
        for (int q = 0; q < 4; q++) acc2[jo][q] = 0.f;

#pragma unroll
    for (int jp = 0; jp < NTW / 2; jp++) {
        float c00 = acc[2*jp][0]   * inv0, c01 = acc[2*jp][1]   * inv0;
        float c02 = acc[2*jp][2]   * inv1, c03 = acc[2*jp][3]   * inv1;
        float c10 = acc[2*jp+1][0] * inv0, c11 = acc[2*jp+1][1] * inv0;
        float c12 = acc[2*jp+1][2] * inv1, c13 = acc[2*jp+1][3] * inv1;

        uint32_t pa_h[4], pa_l[4];
        pa_h[0] = pack_bf2(c00, c01);
        pa_h[1] = pack_bf2(c02, c03);
        pa_h[2] = pack_bf2(c10, c11);
        pa_h[3] = pack_bf2(c12, c13);
        {
            __nv_bfloat162 t0 = *(__nv_bfloat162*)&pa_h[0];
            __nv_bfloat162 t1 = *(__nv_bfloat162*)&pa_h[1];
            __nv_bfloat162 t2 = *(__nv_bfloat162*)&pa_h[2];
            __nv_bfloat162 t3 = *(__nv_bfloat162*)&pa_h[3];
            pa_l[0] = pack_bf2(c00 - __low2float(t0), c01 - __high2float(t0));
            pa_l[1] = pack_bf2(c02 - __low2float(t1), c03 - __high2float(t1));
            pa_l[2] = pack_bf2(c10 - __low2float(t2), c11 - __high2float(t2));
            pa_l[3] = pack_bf2(c12 - __low2float(t3), c13 - __high2float(t3));
        }

        const int k0 = wn * KW + jp * 16;
#pragma unroll
        for (int jo = 0; jo < 8; jo += 2) {
            uint32_t bh[4], bl[4];
            LDSM_X4_T(bh, smaddr(&sVH[(k0 + kt_off) * 72 + jo * 8 + nt_off]));
            LDSM_X4_T(bl, smaddr(&sVL[(k0 + kt_off) * 72 + jo * 8 + nt_off]));
            MMA_BF16(acc2[jo],     pa_h, bh);
            MMA_BF16(acc2[jo],     pa_l, bh);
            MMA_BF16(acc2[jo],     pa_h, bl);
            MMA_BF16(acc2[jo + 1], pa_h, bh + 2);
            MMA_BF16(acc2[jo + 1], pa_l, bh + 2);
            MMA_BF16(acc2[jo + 1], pa_h, bl + 2);
        }
    }

    // ---- cross-warp k-reduction + store (sOut overlays v region, now dead) ----
    __syncthreads();
    if (wn == 0) {
#pragma unroll
        for (int jo = 0; jo < 8; jo++) {
            *(float2*)&sOut[(wm * 16 + qr)     * 72 + jo * 8 + qc] =
                make_float2(acc2[jo][0], acc2[jo][1]);
            *(float2*)&sOut[(wm * 16 + qr + 8) * 72 + jo * 8 + qc] =
                make_float2(acc2[jo][2], acc2[jo][3]);
        }
    }
    __syncthreads();
    if (wn == 1) {
        const int trow0 = base_row + wm * 16 + qr;
#pragma unroll
        for (int jo = 0; jo < 8; jo++) {
            float2 p0 = *(float2*)&sOut[(wm * 16 + qr)     * 72 + jo * 8 + qc];
            float2 p1 = *(float2*)&sOut[(wm * 16 + qr + 8) * 72 + jo * 8 + qc];
            *(float2*)&out[(size_t)trow0 * NH + jo * 8 + qc] =
                make_float2(acc2[jo][0] + p0.x, acc2[jo][1] + p0.y);
            *(float2*)&out[(size_t)(trow0 + 8) * NH + jo * 8 + qc] =
                make_float2(acc2[jo][2] + p1.x, acc2[jo][3] + p1.y);
        }
    }
}

__global__ __launch_bounds__(256, 2) void attn_kernel(const float* __restrict__ x,
                                                      float* __restrict__ out)
{
    const int tb = blockIdx.x;
    const int b  = blockIdx.y;
    if (tb == 0)      attn_body<64 >(x, out, b, 0);
    else if (tb == 1) attn_body<128>(x, out, b, 1);
    else if (tb == 2) attn_body<192>(x, out, b, 2);
    else              attn_body<256>(x, out, b, 3);
}

extern "C" void kernel_launch(void* const* d_in, const int* in_sizes, int n_in,
                              void* d_out, int out_size)
{
    (void)in_sizes; (void)n_in; (void)out_size;
    const float* x   = (const float*)d_in[0];
    const float* Wq  = (const float*)d_in[1];
    const float* Wk  = (const float*)d_in[2];
    const float* Wv  = (const float*)d_in[3];
    const float* Wql = (const float*)d_in[4];
    const float* Wkl = (const float*)d_in[5];
    float* out = (float*)d_out;

    cudaFuncSetAttribute((const void*)attn_kernel,
                         cudaFuncAttributeMaxDynamicSharedMemorySize, ATTN_SMEM_BYTES);
    cudaFuncSetAttribute((const void*)vproj_kernel,
                         cudaFuncAttributeMaxDynamicSharedMemorySize, VPROJ_SMEM);

    convert_wv_kernel<<<(64 * 384 + 255) / 256, 256>>>(Wv);
    wu_kernel<<<384, 256>>>(Wq, Wk, Wql, Wkl);
    vproj_kernel<<<NM / 256, 256, VPROJ_SMEM>>>(x);

    dim3 grid(4, NB);
    attn_kernel<<<grid, 256, ATTN_SMEM_BYTES>>>(x, out);
}

// round 7
// speedup vs baseline: 2.0724x; 1.2588x over previous
#include <cuda_runtime.h>
#include <cuda_fp16.h>
#include <math.h>
#include <stdint.h>

#define NB 512
#define NT 256
#define NC 384
#define NH 64
#define NS 256
#define NM (NB*NT)   // 131072 rows

// scratch (device globals: allocation-guard safe)
__device__ __align__(16) __half g_v[NM * 64];     // v fp16 [row][64]
__device__ __align__(16) __half g_wv[64 * 384];   // Wv [n][k] K-major fp16
__device__ __align__(16) __half g_wu[384 * 256];  // Wu = Wq@Wql + Wk@Wkl, [k][s] fp16

// ---------------- mma.sync / cp.async helpers (baseline PTX ISA) ----------------
#define LDSM_X4(r, addr)                                                        \
    asm volatile("ldmatrix.sync.aligned.m8n8.x4.shared.b16 {%0,%1,%2,%3}, [%4];" \
        : "=r"((r)[0]), "=r"((r)[1]), "=r"((r)[2]), "=r"((r)[3]) : "r"(addr))

#define LDSM_X4_T(r, addr)                                                      \
    asm volatile("ldmatrix.sync.aligned.m8n8.x4.trans.shared.b16 {%0,%1,%2,%3}, [%4];" \
        : "=r"((r)[0]), "=r"((r)[1]), "=r"((r)[2]), "=r"((r)[3]) : "r"(addr))

#define MMA_F16(d, a, b)                                                        \
    asm volatile("mma.sync.aligned.m16n8k16.row.col.f32.f16.f16.f32 "           \
        "{%0,%1,%2,%3}, {%4,%5,%6,%7}, {%8,%9}, {%0,%1,%2,%3};"                 \
        : "+f"((d)[0]), "+f"((d)[1]), "+f"((d)[2]), "+f"((d)[3])                \
        : "r"((a)[0]), "r"((a)[1]), "r"((a)[2]), "r"((a)[3]),                   \
          "r"((b)[0]), "r"((b)[1]))

#define CP_ASYNC16(dst, src)                                                    \
    asm volatile("cp.async.cg.shared.global [%0], [%1], 16;"                    \
        :: "r"(dst), "l"(src))
#define CP_COMMIT  asm volatile("cp.async.commit_group;" ::: "memory")
#define CP_WAIT0   asm volatile("cp.async.wait_group 0;" ::: "memory")

static __device__ __forceinline__ uint32_t pack_h2(float a, float b) {
    __half2 t = __floats2half2_rn(a, b);
    return *(uint32_t*)&t;
}
static __device__ __forceinline__ uint32_t smaddr(const void* p) {
    return (uint32_t)__cvta_generic_to_shared(p);
}

// ---------------- Wu = Wq@Wql + Wk@Wkl  (fp32, then fp16) ----------------
__global__ __launch_bounds__(256) void wu_kernel(
    const float* __restrict__ Wq, const float* __restrict__ Wk,
    const float* __restrict__ Wql, const float* __restrict__ Wkl)
{
    __shared__ float qr_[64], kr_[64];
    const int c = blockIdx.x;
    const int s = threadIdx.x;
    if (s < 64)       qr_[s]      = Wq[c * 64 + s];
    else if (s < 128) kr_[s - 64] = Wk[c * 64 + s - 64];
    __syncthreads();
    float acc = 0.f;
#pragma unroll 8
    for (int h = 0; h < 64; h++)
        acc = fmaf(qr_[h], Wql[h * 256 + s], fmaf(kr_[h], Wkl[h * 256 + s], acc));
    g_wu[c * 256 + s] = __float2half_rn(acc);
}

// ---------------- Wv -> fp16 (K-major) ----------------
__global__ __launch_bounds__(256) void convert_wv_kernel(const float* __restrict__ Wv)
{
    const int idx = blockIdx.x * 256 + threadIdx.x;
    if (idx >= 64 * 384) return;
    const int n = idx / 384, k = idx % 384;
    g_wv[idx] = __float2half_rn(Wv[k * 64 + n]);
}

// ---------------- Kernel A: v projection (x split fp16, Wv fp16) ----------------
// CTA: 256 rows x 64 cols; 8 warps = 4m x 2n; K=384 in 32-chunks.
#define VPROJ_SMEM ((256*40 + 256*40 + 64*40) * 2)

__global__ __launch_bounds__(256) void vproj_kernel(const float* __restrict__ x)
{
    extern __shared__ __half smv[];
    __half* sXH = smv;               // [256][40]
    __half* sXL = sXH + 256 * 40;
    __half* sWH = sXL + 256 * 40;    // [64][40]

    const int tid  = threadIdx.x;
    const int lane = tid & 31;
    const int w    = tid >> 5;
    const int wm   = w & 3;
    const int wn   = w >> 2;
    const int m0   = blockIdx.x * 256;

    const int a_row = (lane & 7) + ((lane >> 3) & 1) * 8;
    const int a_col = (lane >> 4) * 8;
    const int b_row = ((lane >> 4) * 8) + (lane & 7);
    const int b_k8  = ((lane >> 3) & 1) * 8;
    const int qr    = lane >> 2;
    const int qc    = (lane & 3) * 2;

    float acc[4][4][4];
#pragma unroll
    for (int mi = 0; mi < 4; mi++)
#pragma unroll
        for (int ni = 0; ni < 4; ni++)
#pragma unroll
            for (int q = 0; q < 4; q++) acc[mi][ni][q] = 0.f;

    for (int c = 0; c < 12; c++) {
        const int kc = c * 32;
        __syncthreads();
#pragma unroll
        for (int i = 0; i < 8; i++) {
            int idx = tid + 256 * i;
            int row = idx >> 3, seg = idx & 7;
            float4 v = *(const float4*)&x[(size_t)(m0 + row) * NC + kc + seg * 4];
            float vv[4] = {v.x, v.y, v.z, v.w};
            __half h[4], l[4];
#pragma unroll
            for (int j = 0; j < 4; j++) {
                h[j] = __float2half_rn(vv[j]);
                l[j] = __float2half_rn(vv[j] - __half2float(h[j]));
            }
            *(uint2*)&sXH[row * 40 + seg * 4] = *(uint2*)h;
            *(uint2*)&sXL[row * 40 + seg * 4] = *(uint2*)l;
        }
        if (tid < 128) {
            int row = tid >> 1, seg = tid & 1;
            *(uint4*)&sWH[row * 40 + seg * 16] =
                *(const uint4*)&g_wv[(size_t)row * NC + kc + seg * 16];
            *(uint4*)&sWH[row * 40 + seg * 16 + 8] =
                *(const uint4*)&g_wv[(size_t)row * NC + kc + seg * 16 + 8];
        }
        __syncthreads();

#pragma unroll
        for (int kk = 0; kk < 2; kk++) {
            const int k0 = kk * 16;
            uint32_t ah[4][4], al[4][4];
#pragma unroll
            for (int mi = 0; mi < 4; mi++) {
                LDSM_X4(ah[mi], smaddr(&sXH[(wm * 64 + mi * 16 + a_row) * 40 + k0 + a_col]));
                LDSM_X4(al[mi], smaddr(&sXL[(wm * 64 + mi * 16 + a_row) * 40 + k0 + a_col]));
            }
#pragma unroll
            for (int ni = 0; ni < 4; ni += 2) {
                uint32_t bh[4];
                LDSM_X4(bh, smaddr(&sWH[(wn * 32 + ni * 8 + b_row) * 40 + k0 + b_k8]));
#pragma unroll
                for (int mi = 0; mi < 4; mi++) {
                    MMA_F16(acc[mi][ni],     ah[mi], bh);
                    MMA_F16(acc[mi][ni],     al[mi], bh);
                    MMA_F16(acc[mi][ni + 1], ah[mi], bh + 2);
                    MMA_F16(acc[mi][ni + 1], al[mi], bh + 2);
                }
            }
        }
    }

    // epilogue: fp16 store to g_v
#pragma unroll
    for (int mi = 0; mi < 4; mi++) {
        int r0 = m0 + wm * 64 + mi * 16 + qr;
#pragma unroll
        for (int ni = 0; ni < 4; ni++) {
            int col = wn * 32 + ni * 8 + qc;
            *(uint32_t*)&g_v[(size_t)r0 * 64 + col]       = pack_h2(acc[mi][ni][0], acc[mi][ni][1]);
            *(uint32_t*)&g_v[(size_t)(r0 + 8) * 64 + col] = pack_h2(acc[mi][ni][2], acc[mi][ni][3]);
        }
    }
}

// ---------------- Kernel B: fused u-GEMM + softmax + p@v ----------------
// phase1: x (split) + Wu buffers (54.3KB); phase2: v (36.9KB) overlays. 54.8KB total.
#define ATTN_SMEM_BYTES 54784

template <int SLIM>
__device__ __forceinline__ void attn_body(const float* __restrict__ x,
                                          float* __restrict__ out, int b, int tb)
{
    constexpr int SLIMP = SLIM + 8;
    constexpr int NTW   = SLIM / 16;
    constexpr int KW    = SLIM / 2;

    extern __shared__ char smraw[];
    // phase 1
    __half* sXH = (__half*)smraw;            // [2][64][40]
    __half* sXL = sXH + 2 * 64 * 40;
    __half* sWH = sXL + 2 * 64 * 40;         // [2][32][SLIMP]
    // phase 2 (overlays phase 1)
    __half* sV  = (__half*)smraw;            // [SLIM][72]
    float* sOut    = (float*)smraw;          // [64][72], after v dead
    float* rowsumS = (float*)(smraw + 54272);// [2][64]

    const int tid  = threadIdx.x;
    const int lane = tid & 31;
    const int w    = tid >> 5;
    const int wm   = w >> 1;
    const int wn   = w & 1;

    const int a_row  = (lane & 7) + ((lane >> 3) & 1) * 8;
    const int a_col  = (lane >> 4) * 8;
    const int kt_off = (lane & 7) | (((lane >> 3) & 1) << 3);
    const int nt_off = (lane >> 4) * 8;
    const int qr     = lane >> 2;
    const int qc     = (lane & 3) * 2;
    const int base_row = b * NT + tb * 64;

    auto stageX = [&](int c, int buf) {
        const int kc = c * 32;
#pragma unroll
        for (int i = 0; i < 2; i++) {
            int idx = tid + 256 * i;
            int row = idx >> 3, seg = idx & 7;
            float4 v = *(const float4*)&x[(size_t)(base_row + row) * NC + kc + seg * 4];
            float vv[4] = {v.x, v.y, v.z, v.w};
            __half h[4], l[4];
#pragma unroll
            for (int j = 0; j < 4; j++) {
                h[j] = __float2half_rn(vv[j]);
                l[j] = __float2half_rn(vv[j] - __half2float(h[j]));
            }
            *(uint2*)&sXH[buf * 2560 + row * 40 + seg * 4] = *(uint2*)h;
            *(uint2*)&sXL[buf * 2560 + row * 40 + seg * 4] = *(uint2*)l;
        }
    };
    auto stageW = [&](int c, int buf) {      // cp.async 16B fp16 copies
        const int kc = c * 32;
        for (int L = tid; L < 4 * SLIM; L += 256) {
            int r = L / (SLIM / 8), cs = L % (SLIM / 8);
            CP_ASYNC16(smaddr(&sWH[(buf * 32 + r) * SLIMP + cs * 8]),
                       &g_wu[(size_t)(kc + r) * 256 + cs * 8]);
        }
    };

    stageW(0, 0);
    CP_COMMIT;
    stageX(0, 0);
    CP_WAIT0;
    __syncthreads();

    // ---- GEMM1: u = x @ Wu, K=384, 12 chunks double buffered ----
    float acc[NTW][4];
#pragma unroll
    for (int j = 0; j < NTW; j++)
#pragma unroll
        for (int q = 0; q < 4; q++) acc[j][q] = 0.f;

    for (int c = 0; c < 12; c++) {
        const int buf = c & 1;
        if (c < 11) {
            stageW(c + 1, buf ^ 1);
            CP_COMMIT;
            stageX(c + 1, buf ^ 1);
        }
#pragma unroll
        for (int kk = 0; kk < 2; kk++) {
            uint32_t ah[4], al[4];
            LDSM_X4(ah, smaddr(&sXH[buf * 2560 + (wm * 16 + a_row) * 40 + kk * 16 + a_col]));
            LDSM_X4(al, smaddr(&sXL[buf * 2560 + (wm * 16 + a_row) * 40 + kk * 16 + a_col]));
#pragma unroll
            for (int j = 0; j < NTW; j += 2) {
                uint32_t bh[4];
                const int n0 = wn * KW + j * 8 + nt_off;
                LDSM_X4_T(bh, smaddr(&sWH[(buf * 32 + kk * 16 + kt_off) * SLIMP + n0]));
                MMA_F16(acc[j],     ah, bh);
                MMA_F16(acc[j],     al, bh);
                MMA_F16(acc[j + 1], ah, bh + 2);
                MMA_F16(acc[j + 1], al, bh + 2);
            }
        }
        if (c < 11) CP_WAIT0;
        __syncthreads();
    }

    // ---- v staging into dead phase-1 region, overlapped with softmax ----
    for (int L = tid; L < SLIM * 8; L += 256) {
        int s = L >> 3, seg = L & 7;
        CP_ASYNC16(smaddr(&sV[s * 72 + seg * 8]),
                   &g_v[(size_t)(b * NT + s) * 64 + seg * 8]);
    }
    CP_COMMIT;

    // ---- tanh + causal mask + exp + row sums (tanh bounded: no max pass) ----
    const int tg0 = tb * 64 + wm * 16 + qr;
    float rsum0 = 0.f, rsum1 = 0.f;
#pragma unroll
    for (int j = 0; j < NTW; j++) {
        const int c0 = wn * KW + j * 8 + qc;
        float v0 = (c0     <= tg0    ) ? __expf(tanhf(acc[j][0])) : 0.f;
        float v1 = (c0 + 1 <= tg0    ) ? __expf(tanhf(acc[j][1])) : 0.f;
        float v2 = (c0     <= tg0 + 8) ? __expf(tanhf(acc[j][2])) : 0.f;
        float v3 = (c0 + 1 <= tg0 + 8) ? __expf(tanhf(acc[j][3])) : 0.f;
        acc[j][0] = v0; acc[j][1] = v1; acc[j][2] = v2; acc[j][3] = v3;
        rsum0 += v0 + v1;
        rsum1 += v2 + v3;
    }
#pragma unroll
    for (int off = 1; off <= 2; off <<= 1) {
        rsum0 += __shfl_xor_sync(0xffffffffu, rsum0, off);
        rsum1 += __shfl_xor_sync(0xffffffffu, rsum1, off);
    }
    if ((lane & 3) == 0) {
        rowsumS[wn * 64 + wm * 16 + qr]     = rsum0;
        rowsumS[wn * 64 + wm * 16 + qr + 8] = rsum1;
    }
    __syncthreads();
    const float inv0 = 1.f / (rowsumS[wm * 16 + qr]     + rowsumS[64 + wm * 16 + qr]);
    const float inv1 = 1.f / (rowsumS[wm * 16 + qr + 8] + rowsumS[64 + wm * 16 + qr + 8]);

    CP_WAIT0;
    __syncthreads();

    // ---- GEMM2: out += p @ v over k in [wn*KW, wn*KW+KW); p split fp16 ----
    float acc2[8][4];
#pragma unroll
    for (int jo = 0; jo < 8; jo++)
#pragma unroll
        for (int q = 0; q < 4; q++) acc2[jo][q] = 0.f;

#pragma unroll
    for (int jp = 0; jp < NTW / 2; jp++) {
        float c00 = acc[2*jp][0]   * inv0, c01 = acc[2*jp][1]   * inv0;
        float c02 = acc[2*jp][2]   * inv1, c03 = acc[2*jp][3]   * inv1;
        float c10 = acc[2*jp+1][0] * inv0, c11 = acc[2*jp+1][1] * inv0;
        float c12 = acc[2*jp+1][2] * inv1, c13 = acc[2*jp+1][3] * inv1;

        uint32_t pa_h[4], pa_l[4];
        pa_h[0] = pack_h2(c00, c01);
        pa_h[1] = pack_h2(c02, c03);
        pa_h[2] = pack_h2(c10, c11);
        pa_h[3] = pack_h2(c12, c13);
        {
            float2 t0 = __half22float2(*(__half2*)&pa_h[0]);
            float2 t1 = __half22float2(*(__half2*)&pa_h[1]);
            float2 t2 = __half22float2(*(__half2*)&pa_h[2]);
            float2 t3 = __half22float2(*(__half2*)&pa_h[3]);
            pa_l[0] = pack_h2(c00 - t0.x, c01 - t0.y);
            pa_l[1] = pack_h2(c02 - t1.x, c03 - t1.y);
            pa_l[2] = pack_h2(c10 - t2.x, c11 - t2.y);
            pa_l[3] = pack_h2(c12 - t3.x, c13 - t3.y);
        }

        const int k0 = wn * KW + jp * 16;
#pragma unroll
        for (int jo = 0; jo < 8; jo += 2) {
            uint32_t bh[4];
            LDSM_X4_T(bh, smaddr(&sV[(k0 + kt_off) * 72 + jo * 8 + nt_off]));
            MMA_F16(acc2[jo],     pa_h, bh);
            MMA_F16(acc2[jo],     pa_l, bh);
            MMA_F16(acc2[jo + 1], pa_h, bh + 2);
            MMA_F16(acc2[jo + 1], pa_l, bh + 2);
        }
    }

    // ---- cross-warp k-reduction + store ----
    __syncthreads();
    if (wn == 0) {
#pragma unroll
        for (int jo = 0; jo < 8; jo++) {
            *(float2*)&sOut[(wm * 16 + qr)     * 72 + jo * 8 + qc] =
                make_float2(acc2[jo][0], acc2[jo][1]);
            *(float2*)&sOut[(wm * 16 + qr + 8) * 72 + jo * 8 + qc] =
                make_float2(acc2[jo][2], acc2[jo][3]);
        }
    }
    __syncthreads();
    if (wn == 1) {
        const int trow0 = base_row + wm * 16 + qr;
#pragma unroll
        for (int jo = 0; jo < 8; jo++) {
            float2 p0 = *(float2*)&sOut[(wm * 16 + qr)     * 72 + jo * 8 + qc];
            float2 p1 = *(float2*)&sOut[(wm * 16 + qr + 8) * 72 + jo * 8 + qc];
            *(float2*)&out[(size_t)trow0 * NH + jo * 8 + qc] =
                make_float2(acc2[jo][0] + p0.x, acc2[jo][1] + p0.y);
            *(float2*)&out[(size_t)(trow0 + 8) * NH + jo * 8 + qc] =
                make_float2(acc2[jo][2] + p1.x, acc2[jo][3] + p1.y);
        }
    }
}

__global__ __launch_bounds__(256, 2) void attn_kernel(const float* __restrict__ x,
                                                      float* __restrict__ out)
{
    const int tb = blockIdx.x;
    const int b  = blockIdx.y;
    if (tb == 0)      attn_body<64 >(x, out, b, 0);
    else if (tb == 1) attn_body<128>(x, out, b, 1);
    else if (tb == 2) attn_body<192>(x, out, b, 2);
    else              attn_body<256>(x, out, b, 3);
}

extern "C" void kernel_launch(void* const* d_in, const int* in_sizes, int n_in,
                              void* d_out, int out_size)
{
    (void)in_sizes; (void)n_in; (void)out_size;
    const float* x   = (const float*)d_in[0];
    const float* Wq  = (const float*)d_in[1];
    const float* Wk  = (const float*)d_in[2];
    const float* Wv  = (const float*)d_in[3];
    const float* Wql = (const float*)d_in[4];
    const float* Wkl = (const float*)d_in[5];
    float* out = (float*)d_out;

    cudaFuncSetAttribute((const void*)attn_kernel,
                         cudaFuncAttributeMaxDynamicSharedMemorySize, ATTN_SMEM_BYTES);
    cudaFuncSetAttribute((const void*)vproj_kernel,
                         cudaFuncAttributeMaxDynamicSharedMemorySize, VPROJ_SMEM);

    convert_wv_kernel<<<(64 * 384 + 255) / 256, 256>>>(Wv);
    wu_kernel<<<384, 256>>>(Wq, Wk, Wql, Wkl);
    vproj_kernel<<<NM / 256, 256, VPROJ_SMEM>>>(x);

    dim3 grid(4, NB);
    attn_kernel<<<grid, 256, ATTN_SMEM_BYTES>>>(x, out);
}

// round 8
// speedup vs baseline: 2.2035x; 1.0633x over previous
#include <cuda_runtime.h>
#include <cuda_fp16.h>
#include <math.h>
#include <stdint.h>

#define NB 512
#define NT 256
#define NC 384
#define NH 64
#define NS 256
#define NM (NB*NT)   // 131072 rows

// scratch (device globals: allocation-guard safe)
__device__ __align__(16) __half g_v[NM * 64];     // v fp16 [row][64]
__device__ __align__(16) __half g_wv[64 * 384];   // Wv [n][k] K-major fp16
__device__ __align__(16) __half g_wu[384 * 256];  // Wu = Wq@Wql + Wk@Wkl, [k][s] fp16

// ---------------- mma.sync / cp.async helpers (baseline PTX ISA) ----------------
#define LDSM_X4(r, addr)                                                        \
    asm volatile("ldmatrix.sync.aligned.m8n8.x4.shared.b16 {%0,%1,%2,%3}, [%4];" \
        : "=r"((r)[0]), "=r"((r)[1]), "=r"((r)[2]), "=r"((r)[3]) : "r"(addr))

#define LDSM_X4_T(r, addr)                                                      \
    asm volatile("ldmatrix.sync.aligned.m8n8.x4.trans.shared.b16 {%0,%1,%2,%3}, [%4];" \
        : "=r"((r)[0]), "=r"((r)[1]), "=r"((r)[2]), "=r"((r)[3]) : "r"(addr))

#define MMA_F16(d, a, b)                                                        \
    asm volatile("mma.sync.aligned.m16n8k16.row.col.f32.f16.f16.f32 "           \
        "{%0,%1,%2,%3}, {%4,%5,%6,%7}, {%8,%9}, {%0,%1,%2,%3};"                 \
        : "+f"((d)[0]), "+f"((d)[1]), "+f"((d)[2]), "+f"((d)[3])                \
        : "r"((a)[0]), "r"((a)[1]), "r"((a)[2]), "r"((a)[3]),                   \
          "r"((b)[0]), "r"((b)[1]))

#define CP_ASYNC16(dst, src)                                                    \
    asm volatile("cp.async.cg.shared.global [%0], [%1], 16;"                    \
        :: "r"(dst), "l"(src))
#define CP_COMMIT  asm volatile("cp.async.commit_group;" ::: "memory")
#define CP_WAIT0   asm volatile("cp.async.wait_group 0;" ::: "memory")
#define CP_WAIT1   asm volatile("cp.async.wait_group 1;" ::: "memory")

static __device__ __forceinline__ uint32_t pack_h2(float a, float b) {
    __half2 t = __floats2half2_rn(a, b);
    return *(uint32_t*)&t;
}
static __device__ __forceinline__ uint32_t smaddr(const void* p) {
    return (uint32_t)__cvta_generic_to_shared(p);
}

// ---------------- Wu = Wq@Wql + Wk@Wkl  (fp32, then fp16) ----------------
__global__ __launch_bounds__(256) void wu_kernel(
    const float* __restrict__ Wq, const float* __restrict__ Wk,
    const float* __restrict__ Wql, const float* __restrict__ Wkl)
{
    __shared__ float qr_[64], kr_[64];
    const int c = blockIdx.x;
    const int s = threadIdx.x;
    if (s < 64)       qr_[s]      = Wq[c * 64 + s];
    else if (s < 128) kr_[s - 64] = Wk[c * 64 + s - 64];
    __syncthreads();
    float acc = 0.f;
#pragma unroll 8
    for (int h = 0; h < 64; h++)
        acc = fmaf(qr_[h], Wql[h * 256 + s], fmaf(kr_[h], Wkl[h * 256 + s], acc));
    g_wu[c * 256 + s] = __float2half_rn(acc);
}

// ---------------- Wv -> fp16 (K-major) ----------------
__global__ __launch_bounds__(256) void convert_wv_kernel(const float* __restrict__ Wv)
{
    const int idx = blockIdx.x * 256 + threadIdx.x;
    if (idx >= 64 * 384) return;
    const int n = idx / 384, k = idx % 384;
    g_wv[idx] = __float2half_rn(Wv[k * 64 + n]);
}

// ---------------- Kernel A: v projection (x split fp16, Wv fp16) ----------------
#define VPROJ_SMEM ((256*40 + 256*40 + 64*40) * 2)

__global__ __launch_bounds__(256) void vproj_kernel(const float* __restrict__ x)
{
    extern __shared__ __half smv[];
    __half* sXH = smv;               // [256][40]
    __half* sXL = sXH + 256 * 40;
    __half* sWH = sXL + 256 * 40;    // [64][40]

    const int tid  = threadIdx.x;
    const int lane = tid & 31;
    const int w    = tid >> 5;
    const int wm   = w & 3;
    const int wn   = w >> 2;
    const int m0   = blockIdx.x * 256;

    const int a_row = (lane & 7) + ((lane >> 3) & 1) * 8;
    const int a_col = (lane >> 4) * 8;
    const int b_row = ((lane >> 4) * 8) + (lane & 7);
    const int b_k8  = ((lane >> 3) & 1) * 8;
    const int qr    = lane >> 2;
    const int qc    = (lane & 3) * 2;

    float acc[4][4][4];
#pragma unroll
    for (int mi = 0; mi < 4; mi++)
#pragma unroll
        for (int ni = 0; ni < 4; ni++)
#pragma unroll
            for (int q = 0; q < 4; q++) acc[mi][ni][q] = 0.f;

    for (int c = 0; c < 12; c++) {
        const int kc = c * 32;
        __syncthreads();
#pragma unroll
        for (int i = 0; i < 8; i++) {
            int idx = tid + 256 * i;
            int row = idx >> 3, seg = idx & 7;
            float4 v = *(const float4*)&x[(size_t)(m0 + row) * NC + kc + seg * 4];
            float vv[4] = {v.x, v.y, v.z, v.w};
            __half h[4], l[4];
#pragma unroll
            for (int j = 0; j < 4; j++) {
                h[j] = __float2half_rn(vv[j]);
                l[j] = __float2half_rn(vv[j] - __half2float(h[j]));
            }
            *(uint2*)&sXH[row * 40 + seg * 4] = *(uint2*)h;
            *(uint2*)&sXL[row * 40 + seg * 4] = *(uint2*)l;
        }
        if (tid < 128) {
            int row = tid >> 1, seg = tid & 1;
            *(uint4*)&sWH[row * 40 + seg * 16] =
                *(const uint4*)&g_wv[(size_t)row * NC + kc + seg * 16];
            *(uint4*)&sWH[row * 40 + seg * 16 + 8] =
                *(const uint4*)&g_wv[(size_t)row * NC + kc + seg * 16 + 8];
        }
        __syncthreads();

#pragma unroll
        for (int kk = 0; kk < 2; kk++) {
            const int k0 = kk * 16;
            uint32_t ah[4][4], al[4][4];
#pragma unroll
            for (int mi = 0; mi < 4; mi++) {
                LDSM_X4(ah[mi], smaddr(&sXH[(wm * 64 + mi * 16 + a_row) * 40 + k0 + a_col]));
                LDSM_X4(al[mi], smaddr(&sXL[(wm * 64 + mi * 16 + a_row) * 40 + k0 + a_col]));
            }
#pragma unroll
            for (int ni = 0; ni < 4; ni += 2) {
                uint32_t bh[4];
                LDSM_X4(bh, smaddr(&sWH[(wn * 32 + ni * 8 + b_row) * 40 + k0 + b_k8]));
#pragma unroll
                for (int mi = 0; mi < 4; mi++) {
                    MMA_F16(acc[mi][ni],     ah[mi], bh);
                    MMA_F16(acc[mi][ni],     al[mi], bh);
                    MMA_F16(acc[mi][ni + 1], ah[mi], bh + 2);
                    MMA_F16(acc[mi][ni + 1], al[mi], bh + 2);
                }
            }
        }
    }

#pragma unroll
    for (int mi = 0; mi < 4; mi++) {
        int r0 = m0 + wm * 64 + mi * 16 + qr;
#pragma unroll
        for (int ni = 0; ni < 4; ni++) {
            int col = wn * 32 + ni * 8 + qc;
            *(uint32_t*)&g_v[(size_t)r0 * 64 + col]       = pack_h2(acc[mi][ni][0], acc[mi][ni][1]);
            *(uint32_t*)&g_v[(size_t)(r0 + 8) * 64 + col] = pack_h2(acc[mi][ni][2], acc[mi][ni][3]);
        }
    }
}

// ---------------- Kernel B: fused u-GEMM + softmax + p@v ----------------
// 3-stage cp.async pipeline; phase2 v overlays phase-1 buffers. 81.9KB, 2 CTAs/SM.
#define ATTN_SMEM_BYTES 81920

template <int SLIM>
__device__ __forceinline__ void attn_body(const float* __restrict__ x,
                                          float* __restrict__ out, int b, int tb)
{
    constexpr int SLIMP = SLIM + 8;
    constexpr int NTW   = SLIM / 16;
    constexpr int KW    = SLIM / 2;
    constexpr int XBUF  = 64 * 40;      // halves per x buffer

    extern __shared__ char smraw[];
    // phase 1 (3-stage)
    __half* sXH = (__half*)smraw;            // [3][64][40]
    __half* sXL = sXH + 3 * XBUF;
    __half* sWH = sXL + 3 * XBUF;            // [3][32][SLIMP]
    // phase 2 (overlays phase 1)
    __half* sV  = (__half*)smraw;            // [SLIM][72]
    float* sOut    = (float*)smraw;          // [64][72], after v dead
    float* rowsumS = (float*)(smraw + 81408);// [2][64]

    const int tid  = threadIdx.x;
    const int lane = tid & 31;
    const int w    = tid >> 5;
    const int wm   = w >> 1;
    const int wn   = w & 1;

    const int a_row  = (lane & 7) + ((lane >> 3) & 1) * 8;
    const int a_col  = (lane >> 4) * 8;
    const int kt_off = (lane & 7) | (((lane >> 3) & 1) << 3);
    const int nt_off = (lane >> 4) * 8;
    const int qr     = lane >> 2;
    const int qc     = (lane & 3) * 2;
    const int base_row = b * NT + tb * 64;

    auto stageX = [&](int c, int buf) {
        const int kc = c * 32;
#pragma unroll
        for (int i = 0; i < 2; i++) {
            int idx = tid + 256 * i;
            int row = idx >> 3, seg = idx & 7;
            float4 v = *(const float4*)&x[(size_t)(base_row + row) * NC + kc + seg * 4];
            float vv[4] = {v.x, v.y, v.z, v.w};
            __half h[4], l[4];
#pragma unroll
            for (int j = 0; j < 4; j++) {
                h[j] = __float2half_rn(vv[j]);
                l[j] = __float2half_rn(vv[j] - __half2float(h[j]));
            }
            *(uint2*)&sXH[buf * XBUF + row * 40 + seg * 4] = *(uint2*)h;
            *(uint2*)&sXL[buf * XBUF + row * 40 + seg * 4] = *(uint2*)l;
        }
    };
    auto stageW = [&](int c, int buf) {      // cp.async 16B fp16 copies
        const int kc = c * 32;
        for (int L = tid; L < 4 * SLIM; L += 256) {
            int r = L / (SLIM / 8), cs = L % (SLIM / 8);
            CP_ASYNC16(smaddr(&sWH[(buf * 32 + r) * SLIMP + cs * 8]),
                       &g_wu[(size_t)(kc + r) * 256 + cs * 8]);
        }
    };

    // prologue: stages 0,1
    stageW(0, 0); CP_COMMIT; stageX(0, 0);
    stageW(1, 1); CP_COMMIT; stageX(1, 1);

    // ---- GEMM1: u = x @ Wu, K=384, 12 chunks, 3-stage pipeline ----
    float acc[NTW][4];
#pragma unroll
    for (int j = 0; j < NTW; j++)
#pragma unroll
        for (int q = 0; q < 4; q++) acc[j][q] = 0.f;

    for (int c = 0; c < 12; c++) {
        if (c == 11) { CP_WAIT0; } else { CP_WAIT1; }
        __syncthreads();
        if (c + 2 < 12) {
            stageW(c + 2, (c + 2) % 3);
            CP_COMMIT;
            stageX(c + 2, (c + 2) % 3);
        }
        const int buf = c % 3;
#pragma unroll
        for (int kk = 0; kk < 2; kk++) {
            uint32_t ah[4], al[4];
            LDSM_X4(ah, smaddr(&sXH[buf * XBUF + (wm * 16 + a_row) * 40 + kk * 16 + a_col]));
            LDSM_X4(al, smaddr(&sXL[buf * XBUF + (wm * 16 + a_row) * 40 + kk * 16 + a_col]));
#pragma unroll
            for (int j = 0; j < NTW; j += 2) {
                uint32_t bh[4];
                const int n0 = wn * KW + j * 8 + nt_off;
                LDSM_X4_T(bh, smaddr(&sWH[(buf * 32 + kk * 16 + kt_off) * SLIMP + n0]));
                MMA_F16(acc[j],     ah, bh);
                MMA_F16(acc[j],     al, bh);
                MMA_F16(acc[j + 1], ah, bh + 2);
                MMA_F16(acc[j + 1], al, bh + 2);
            }
        }
    }
    __syncthreads();   // all reads of phase-1 buffers done before v overlay

    // ---- v staging into dead phase-1 region, overlapped with softmax ----
    for (int L = tid; L < SLIM * 8; L += 256) {
        int s = L >> 3, seg = L & 7;
        CP_ASYNC16(smaddr(&sV[s * 72 + seg * 8]),
                   &g_v[(size_t)(b * NT + s) * 64 + seg * 8]);
    }
    CP_COMMIT;

    // ---- tanh + causal mask + exp + row sums (tanh bounded: no max pass) ----
    const int tg0 = tb * 64 + wm * 16 + qr;
    float rsum0 = 0.f, rsum1 = 0.f;
#pragma unroll
    for (int j = 0; j < NTW; j++) {
        const int c0 = wn * KW + j * 8 + qc;
        float v0 = (c0     <= tg0    ) ? __expf(tanhf(acc[j][0])) : 0.f;
        float v1 = (c0 + 1 <= tg0    ) ? __expf(tanhf(acc[j][1])) : 0.f;
        float v2 = (c0     <= tg0 + 8) ? __expf(tanhf(acc[j][2])) : 0.f;
        float v3 = (c0 + 1 <= tg0 + 8) ? __expf(tanhf(acc[j][3])) : 0.f;
        acc[j][0] = v0; acc[j][1] = v1; acc[j][2] = v2; acc[j][3] = v3;
        rsum0 += v0 + v1;
        rsum1 += v2 + v3;
    }
#pragma unroll
    for (int off = 1; off <= 2; off <<= 1) {
        rsum0 += __shfl_xor_sync(0xffffffffu, rsum0, off);
        rsum1 += __shfl_xor_sync(0xffffffffu, rsum1, off);
    }
    if ((lane & 3) == 0) {
        rowsumS[wn * 64 + wm * 16 + qr]     = rsum0;
        rowsumS[wn * 64 + wm * 16 + qr + 8] = rsum1;
    }
    __syncthreads();
    const float inv0 = 1.f / (rowsumS[wm * 16 + qr]     + rowsumS[64 + wm * 16 + qr]);
    const float inv1 = 1.f / (rowsumS[wm * 16 + qr + 8] + rowsumS[64 + wm * 16 + qr + 8]);

    CP_WAIT0;
    __syncthreads();

    // ---- GEMM2: out += p @ v over k in [wn*KW, wn*KW+KW); p split fp16 ----
    float acc2[8][4];
#pragma unroll
    for (int jo = 0; jo < 8; jo++)
#pragma unroll
        for (int q = 0; q < 4; q++) acc2[jo][q] = 0.f;

#pragma unroll
    for (int jp = 0; jp < NTW / 2; jp++) {
        float c00 = acc[2*jp][0]   * inv0, c01 = acc[2*jp][1]   * inv0;
        float c02 = acc[2*jp][2]   * inv1, c03 = acc[2*jp][3]   * inv1;
        float c10 = acc[2*jp+1][0] * inv0, c11 = acc[2*jp+1][1] * inv0;
        float c12 = acc[2*jp+1][2] * inv1, c13 = acc[2*jp+1][3] * inv1;

        uint32_t pa_h[4], pa_l[4];
        pa_h[0] = pack_h2(c00, c01);
        pa_h[1] = pack_h2(c02, c03);
        pa_h[2] = pack_h2(c10, c11);
        pa_h[3] = pack_h2(c12, c13);
        {
            float2 t0 = __half22float2(*(__half2*)&pa_h[0]);
            float2 t1 = __half22float2(*(__half2*)&pa_h[1]);
            float2 t2 = __half22float2(*(__half2*)&pa_h[2]);
            float2 t3 = __half22float2(*(__half2*)&pa_h[3]);
            pa_l[0] = pack_h2(c00 - t0.x, c01 - t0.y);
            pa_l[1] = pack_h2(c02 - t1.x, c03 - t1.y);
            pa_l[2] = pack_h2(c10 - t2.x, c11 - t2.y);
            pa_l[3] = pack_h2(c12 - t3.x, c13 - t3.y);
        }

        const int k0 = wn * KW + jp * 16;
#pragma unroll
        for (int jo = 0; jo < 8; jo += 2) {
            uint32_t bh[4];
            LDSM_X4_T(bh, smaddr(&sV[(k0 + kt_off) * 72 + jo * 8 + nt_off]));
            MMA_F16(acc2[jo],     pa_h, bh);
            MMA_F16(acc2[jo],     pa_l, bh);
            MMA_F16(acc2[jo + 1], pa_h, bh + 2);
            MMA_F16(acc2[jo + 1], pa_l, bh + 2);
        }
    }

    // ---- cross-warp k-reduction + store ----
    __syncthreads();
    if (wn == 0) {
#pragma unroll
        for (int jo = 0; jo < 8; jo++) {
            *(float2*)&sOut[(wm * 16 + qr)     * 72 + jo * 8 + qc] =
                make_float2(acc2[jo][0], acc2[jo][1]);
            *(float2*)&sOut[(wm * 16 + qr + 8) * 72 + jo * 8 + qc] =
                make_float2(acc2[jo][2], acc2[jo][3]);
        }
    }
    __syncthreads();
    if (wn == 1) {
        const int trow0 = base_row + wm * 16 + qr;
#pragma unroll
        for (int jo = 0; jo < 8; jo++) {
            float2 p0 = *(float2*)&sOut[(wm * 16 + qr)     * 72 + jo * 8 + qc];
            float2 p1 = *(float2*)&sOut[(wm * 16 + qr + 8) * 72 + jo * 8 + qc];
            *(float2*)&out[(size_t)trow0 * NH + jo * 8 + qc] =
                make_float2(acc2[jo][0] + p0.x, acc2[jo][1] + p0.y);
            *(float2*)&out[(size_t)(trow0 + 8) * NH + jo * 8 + qc] =
                make_float2(acc2[jo][2] + p1.x, acc2[jo][3] + p1.y);
        }
    }
}

__global__ __launch_bounds__(256, 2) void attn_kernel(const float* __restrict__ x,
                                                      float* __restrict__ out)
{
    // heavy-first 1D order: bid 0-511 -> tb=3 (SLIM=256), ..., 1536-2047 -> tb=0
    const int bid = blockIdx.x;
    const int tb  = 3 - (bid >> 9);
    const int b   = bid & 511;
    if (tb == 3)      attn_body<256>(x, out, b, 3);
    else if (tb == 2) attn_body<192>(x, out, b, 2);
    else if (tb == 1) attn_body<128>(x, out, b, 1);
    else              attn_body<64 >(x, out, b, 0);
}

extern "C" void kernel_launch(void* const* d_in, const int* in_sizes, int n_in,
                              void* d_out, int out_size)
{
    (void)in_sizes; (void)n_in; (void)out_size;
    const float* x   = (const float*)d_in[0];
    const float* Wq  = (const float*)d_in[1];
    const float* Wk  = (const float*)d_in[2];
    const float* Wv  = (const float*)d_in[3];
    const float* Wql = (const float*)d_in[4];
    const float* Wkl = (const float*)d_in[5];
    float* out = (float*)d_out;

    cudaFuncSetAttribute((const void*)attn_kernel,
                         cudaFuncAttributeMaxDynamicSharedMemorySize, ATTN_SMEM_BYTES);
    cudaFuncSetAttribute((const void*)vproj_kernel,
                         cudaFuncAttributeMaxDynamicSharedMemorySize, VPROJ_SMEM);

    convert_wv_kernel<<<(64 * 384 + 255) / 256, 256>>>(Wv);
    wu_kernel<<<384, 256>>>(Wq, Wk, Wql, Wkl);
    vproj_kernel<<<NM / 256, 256, VPROJ_SMEM>>>(x);

    attn_kernel<<<2048, 256, ATTN_SMEM_BYTES>>>(x, out);
}

// round 9
// speedup vs baseline: 2.2547x; 1.0232x over previous
#include <cuda_runtime.h>
#include <cuda_fp16.h>
#include <math.h>
#include <stdint.h>

#define NB 512
#define NT 256
#define NC 384
#define NH 64
#define NS 256
#define NM (NB*NT)   // 131072 rows

// scratch (device globals: allocation-guard safe)
__device__ __align__(16) __half g_v[NM * 64];     // v fp16 [row][64]
__device__ __align__(16) __half g_wv[64 * 384];   // Wv [n][k] K-major fp16
__device__ __align__(16) __half g_wu[384 * 256];  // Wu = Wq@Wql + Wk@Wkl, [k][s] fp16

// ---------------- mma.sync / cp.async helpers (baseline PTX ISA) ----------------
#define LDSM_X4(r, addr)                                                        \
    asm volatile("ldmatrix.sync.aligned.m8n8.x4.shared.b16 {%0,%1,%2,%3}, [%4];" \
        : "=r"((r)[0]), "=r"((r)[1]), "=r"((r)[2]), "=r"((r)[3]) : "r"(addr))

#define LDSM_X4_T(r, addr)                                                      \
    asm volatile("ldmatrix.sync.aligned.m8n8.x4.trans.shared.b16 {%0,%1,%2,%3}, [%4];" \
        : "=r"((r)[0]), "=r"((r)[1]), "=r"((r)[2]), "=r"((r)[3]) : "r"(addr))

#define MMA_F16(d, a, b)                                                        \
    asm volatile("mma.sync.aligned.m16n8k16.row.col.f32.f16.f16.f32 "           \
        "{%0,%1,%2,%3}, {%4,%5,%6,%7}, {%8,%9}, {%0,%1,%2,%3};"                 \
        : "+f"((d)[0]), "+f"((d)[1]), "+f"((d)[2]), "+f"((d)[3])                \
        : "r"((a)[0]), "r"((a)[1]), "r"((a)[2]), "r"((a)[3]),                   \
          "r"((b)[0]), "r"((b)[1]))

#define CP_ASYNC16(dst, src)                                                    \
    asm volatile("cp.async.cg.shared.global [%0], [%1], 16;"                    \
        :: "r"(dst), "l"(src))
#define CP_COMMIT  asm volatile("cp.async.commit_group;" ::: "memory")
#define CP_WAIT0   asm volatile("cp.async.wait_group 0;" ::: "memory")
#define CP_WAIT1   asm volatile("cp.async.wait_group 1;" ::: "memory")

static __device__ __forceinline__ uint32_t pack_h2(float a, float b) {
    __half2 t = __floats2half2_rn(a, b);
    return *(uint32_t*)&t;
}
static __device__ __forceinline__ uint32_t smaddr(const void* p) {
    return (uint32_t)__cvta_generic_to_shared(p);
}
static __device__ __forceinline__ float tanh_fast(float v) {
    float y;
    asm("tanh.approx.f32 %0, %1;" : "=f"(y) : "f"(v));
    return y;
}

// ---------------- Wu = Wq@Wql + Wk@Wkl  (fp32, then fp16) ----------------
__global__ __launch_bounds__(256) void wu_kernel(
    const float* __restrict__ Wq, const float* __restrict__ Wk,
    const float* __restrict__ Wql, const float* __restrict__ Wkl)
{
    __shared__ float qr_[64], kr_[64];
    const int c = blockIdx.x;
    const int s = threadIdx.x;
    if (s < 64)       qr_[s]      = Wq[c * 64 + s];
    else if (s < 128) kr_[s - 64] = Wk[c * 64 + s - 64];
    __syncthreads();
    float acc = 0.f;
#pragma unroll 8
    for (int h = 0; h < 64; h++)
        acc = fmaf(qr_[h], Wql[h * 256 + s], fmaf(kr_[h], Wkl[h * 256 + s], acc));
    g_wu[c * 256 + s] = __float2half_rn(acc);
}

// ---------------- Wv -> fp16 (K-major) ----------------
__global__ __launch_bounds__(256) void convert_wv_kernel(const float* __restrict__ Wv)
{
    const int idx = blockIdx.x * 256 + threadIdx.x;
    if (idx >= 64 * 384) return;
    const int n = idx / 384, k = idx % 384;
    g_wv[idx] = __float2half_rn(Wv[k * 64 + n]);
}

// ---------------- Kernel A: v projection (x split fp16, Wv fp16) ----------------
#define VPROJ_SMEM ((256*40 + 256*40 + 64*40) * 2)

__global__ __launch_bounds__(256) void vproj_kernel(const float* __restrict__ x)
{
    extern __shared__ __half smv[];
    __half* sXH = smv;               // [256][40]
    __half* sXL = sXH + 256 * 40;
    __half* sWH = sXL + 256 * 40;    // [64][40]

    const int tid  = threadIdx.x;
    const int lane = tid & 31;
    const int w    = tid >> 5;
    const int wm   = w & 3;
    const int wn   = w >> 2;
    const int m0   = blockIdx.x * 256;

    const int a_row = (lane & 7) + ((lane >> 3) & 1) * 8;
    const int a_col = (lane >> 4) * 8;
    const int b_row = ((lane >> 4) * 8) + (lane & 7);
    const int b_k8  = ((lane >> 3) & 1) * 8;
    const int qr    = lane >> 2;
    const int qc    = (lane & 3) * 2;

    float acc[4][4][4];
#pragma unroll
    for (int mi = 0; mi < 4; mi++)
#pragma unroll
        for (int ni = 0; ni < 4; ni++)
#pragma unroll
            for (int q = 0; q < 4; q++) acc[mi][ni][q] = 0.f;

    for (int c = 0; c < 12; c++) {
        const int kc = c * 32;
        __syncthreads();
#pragma unroll
        for (int i = 0; i < 8; i++) {
            int idx = tid + 256 * i;
            int row = idx >> 3, seg = idx & 7;
            float4 v = *(const float4*)&x[(size_t)(m0 + row) * NC + kc + seg * 4];
            float vv[4] = {v.x, v.y, v.z, v.w};
            __half h[4], l[4];
#pragma unroll
            for (int j = 0; j < 4; j++) {
                h[j] = __float2half_rn(vv[j]);
                l[j] = __float2half_rn(vv[j] - __half2float(h[j]));
            }
            *(uint2*)&sXH[row * 40 + seg * 4] = *(uint2*)h;
            *(uint2*)&sXL[row * 40 + seg * 4] = *(uint2*)l;
        }
        if (tid < 128) {
            int row = tid >> 1, seg = tid & 1;
            *(uint4*)&sWH[row * 40 + seg * 16] =
                *(const uint4*)&g_wv[(size_t)row * NC + kc + seg * 16];
            *(uint4*)&sWH[row * 40 + seg * 16 + 8] =
                *(const uint4*)&g_wv[(size_t)row * NC + kc + seg * 16 + 8];
        }
        __syncthreads();

#pragma unroll
        for (int kk = 0; kk < 2; kk++) {
            const int k0 = kk * 16;
            uint32_t ah[4][4], al[4][4];
#pragma unroll
            for (int mi = 0; mi < 4; mi++) {
                LDSM_X4(ah[mi], smaddr(&sXH[(wm * 64 + mi * 16 + a_row) * 40 + k0 + a_col]));
                LDSM_X4(al[mi], smaddr(&sXL[(wm * 64 + mi * 16 + a_row) * 40 + k0 + a_col]));
            }
#pragma unroll
            for (int ni = 0; ni < 4; ni += 2) {
                uint32_t bh[4];
                LDSM_X4(bh, smaddr(&sWH[(wn * 32 + ni * 8 + b_row) * 40 + k0 + b_k8]));
#pragma unroll
                for (int mi = 0; mi < 4; mi++) {
                    MMA_F16(acc[mi][ni],     ah[mi], bh);
                    MMA_F16(acc[mi][ni],     al[mi], bh);
                    MMA_F16(acc[mi][ni + 1], ah[mi], bh + 2);
                    MMA_F16(acc[mi][ni + 1], al[mi], bh + 2);
                }
            }
        }
    }

#pragma unroll
    for (int mi = 0; mi < 4; mi++) {
        int r0 = m0 + wm * 64 + mi * 16 + qr;
#pragma unroll
        for (int ni = 0; ni < 4; ni++) {
            int col = wn * 32 + ni * 8 + qc;
            *(uint32_t*)&g_v[(size_t)r0 * 64 + col]       = pack_h2(acc[mi][ni][0], acc[mi][ni][1]);
            *(uint32_t*)&g_v[(size_t)(r0 + 8) * 64 + col] = pack_h2(acc[mi][ni][2], acc[mi][ni][3]);
        }
    }
}

// ---------------- Kernel B: fused u-GEMM + softmax + p@v ----------------
// 3-stage cp.async pipeline; v overlays phase-1; causal tile-skip. 81.9KB, 2 CTAs/SM.
#define ATTN_SMEM_BYTES 81920

template <int SLIM>
__device__ __forceinline__ void attn_body(const float* __restrict__ x,
                                          float* __restrict__ out, int b, int tb)
{
    constexpr int SLIMP = SLIM + 8;
    constexpr int NTW   = SLIM / 16;
    constexpr int KW    = SLIM / 2;
    constexpr int XBUF  = 64 * 40;      // halves per x buffer

    extern __shared__ char smraw[];
    // phase 1 (3-stage)
    __half* sXH = (__half*)smraw;            // [3][64][40]
    __half* sXL = sXH + 3 * XBUF;
    __half* sWH = sXL + 3 * XBUF;            // [3][32][SLIMP]
    // phase 2 (overlays phase 1)
    __half* sV  = (__half*)smraw;            // [SLIM][72]
    float* sOut    = (float*)smraw;          // [64][72], after v dead
    float* rowsumS = (float*)(smraw + 81408);// [2][64]

    const int tid  = threadIdx.x;
    const int lane = tid & 31;
    const int w    = tid >> 5;
    const int wm   = w >> 1;
    const int wn   = w & 1;

    const int a_row  = (lane & 7) + ((lane >> 3) & 1) * 8;
    const int a_col  = (lane >> 4) * 8;
    const int kt_off = (lane & 7) | (((lane >> 3) & 1) << 3);
    const int nt_off = (lane >> 4) * 8;
    const int qr     = lane >> 2;
    const int qc     = (lane & 3) * 2;
    const int base_row = b * NT + tb * 64;

    // causal limit for this warp's row range (max t index)
    const int limit = tb * 64 + wm * 16 + 15;
    const int nw0   = wn * KW;

    auto stageX = [&](int c, int buf) {
        const int kc = c * 32;
#pragma unroll
        for (int i = 0; i < 2; i++) {
            int idx = tid + 256 * i;
            int row = idx >> 3, seg = idx & 7;
            float4 v = *(const float4*)&x[(size_t)(base_row + row) * NC + kc + seg * 4];
            float vv[4] = {v.x, v.y, v.z, v.w};
            __half h[4], l[4];
#pragma unroll
            for (int j = 0; j < 4; j++) {
                h[j] = __float2half_rn(vv[j]);
                l[j] = __float2half_rn(vv[j] - __half2float(h[j]));
            }
            *(uint2*)&sXH[buf * XBUF + row * 40 + seg * 4] = *(uint2*)h;
            *(uint2*)&sXL[buf * XBUF + row * 40 + seg * 4] = *(uint2*)l;
        }
    };
    auto stageW = [&](int c, int buf) {      // cp.async 16B fp16 copies
        const int kc = c * 32;
        for (int L = tid; L < 4 * SLIM; L += 256) {
            int r = L / (SLIM / 8), cs = L % (SLIM / 8);
            CP_ASYNC16(smaddr(&sWH[(buf * 32 + r) * SLIMP + cs * 8]),
                       &g_wu[(size_t)(kc + r) * 256 + cs * 8]);
        }
    };

    // prologue: stages 0,1
    stageW(0, 0); CP_COMMIT; stageX(0, 0);
    stageW(1, 1); CP_COMMIT; stageX(1, 1);

    // ---- GEMM1: u = x @ Wu, K=384, 12 chunks, 3-stage pipeline ----
    float acc[NTW][4];
#pragma unroll
    for (int j = 0; j < NTW; j++)
#pragma unroll
        for (int q = 0; q < 4; q++) acc[j][q] = 0.f;

    for (int c = 0; c < 12; c++) {
        if (c == 11) { CP_WAIT0; } else { CP_WAIT1; }
        __syncthreads();
        if (c + 2 < 12) {
            stageW(c + 2, (c + 2) % 3);
            CP_COMMIT;
            stageX(c + 2, (c + 2) % 3);
        }
        const int buf = c % 3;
#pragma unroll
        for (int kk = 0; kk < 2; kk++) {
            uint32_t ah[4], al[4];
            LDSM_X4(ah, smaddr(&sXH[buf * XBUF + (wm * 16 + a_row) * 40 + kk * 16 + a_col]));
            LDSM_X4(al, smaddr(&sXL[buf * XBUF + (wm * 16 + a_row) * 40 + kk * 16 + a_col]));
#pragma unroll
            for (int j = 0; j < NTW; j += 2) {
                const int n0 = nw0 + j * 8;
                if (n0 <= limit) {   // warp-uniform causal tile-pair skip
                    uint32_t bh[4];
                    LDSM_X4_T(bh, smaddr(&sWH[(buf * 32 + kk * 16 + kt_off) * SLIMP + n0 + nt_off]));
                    MMA_F16(acc[j],     ah, bh);
                    MMA_F16(acc[j],     al, bh);
                    MMA_F16(acc[j + 1], ah, bh + 2);
                    MMA_F16(acc[j + 1], al, bh + 2);
                }
            }
        }
    }
    __syncthreads();   // all reads of phase-1 buffers done before v overlay

    // ---- v staging into dead phase-1 region, overlapped with softmax ----
    for (int L = tid; L < SLIM * 8; L += 256) {
        int s = L >> 3, seg = L & 7;
        CP_ASYNC16(smaddr(&sV[s * 72 + seg * 8]),
                   &g_v[(size_t)(b * NT + s) * 64 + seg * 8]);
    }
    CP_COMMIT;

    // ---- tanh + causal mask + exp + row sums (tanh bounded: no max pass) ----
    const int tg0 = tb * 64 + wm * 16 + qr;
    float rsum0 = 0.f, rsum1 = 0.f;
#pragma unroll
    for (int j = 0; j < NTW; j++) {
        const int c0 = nw0 + j * 8 + qc;
        if (nw0 + j * 8 <= limit) {
            float v0 = (c0     <= tg0    ) ? __expf(tanh_fast(acc[j][0])) : 0.f;
            float v1 = (c0 + 1 <= tg0    ) ? __expf(tanh_fast(acc[j][1])) : 0.f;
            float v2 = (c0     <= tg0 + 8) ? __expf(tanh_fast(acc[j][2])) : 0.f;
            float v3 = (c0 + 1 <= tg0 + 8) ? __expf(tanh_fast(acc[j][3])) : 0.f;
            acc[j][0] = v0; acc[j][1] = v1; acc[j][2] = v2; acc[j][3] = v3;
            rsum0 += v0 + v1;
            rsum1 += v2 + v3;
        } else {
            // tile may hold garbage from pair-granularity GEMM1: force zero
            acc[j][0] = 0.f; acc[j][1] = 0.f; acc[j][2] = 0.f; acc[j][3] = 0.f;
        }
    }
#pragma unroll
    for (int off = 1; off <= 2; off <<= 1) {
        rsum0 += __shfl_xor_sync(0xffffffffu, rsum0, off);
        rsum1 += __shfl_xor_sync(0xffffffffu, rsum1, off);
    }
    if ((lane & 3) == 0) {
        rowsumS[wn * 64 + wm * 16 + qr]     = rsum0;
        rowsumS[wn * 64 + wm * 16 + qr + 8] = rsum1;
    }
    __syncthreads();
    const float inv0 = 1.f / (rowsumS[wm * 16 + qr]     + rowsumS[64 + wm * 16 + qr]);
    const float inv1 = 1.f / (rowsumS[wm * 16 + qr + 8] + rowsumS[64 + wm * 16 + qr + 8]);

    CP_WAIT0;
    __syncthreads();

    // ---- GEMM2: out += p @ v over k in [wn*KW, wn*KW+KW); p split fp16 ----
    float acc2[8][4];
#pragma unroll
    for (int jo = 0; jo < 8; jo++)
#pragma unroll
        for (int q = 0; q < 4; q++) acc2[jo][q] = 0.f;

#pragma unroll
    for (int jp = 0; jp < NTW / 2; jp++) {
        const int k0 = nw0 + jp * 16;
        if (k0 <= limit) {   // warp-uniform causal k-pair skip
            float c00 = acc[2*jp][0]   * inv0, c01 = acc[2*jp][1]   * inv0;
            float c02 = acc[2*jp][2]   * inv1, c03 = acc[2*jp][3]   * inv1;
            float c10 = acc[2*jp+1][0] * inv0, c11 = acc[2*jp+1][1] * inv0;
            float c12 = acc[2*jp+1][2] * inv1, c13 = acc[2*jp+1][3] * inv1;

            uint32_t pa_h[4], pa_l[4];
            pa_h[0] = pack_h2(c00, c01);
            pa_h[1] = pack_h2(c02, c03);
            pa_h[2] = pack_h2(c10, c11);
            pa_h[3] = pack_h2(c12, c13);
            {
                float2 t0 = __half22float2(*(__half2*)&pa_h[0]);
                float2 t1 = __half22float2(*(__half2*)&pa_h[1]);
                float2 t2 = __half22float2(*(__half2*)&pa_h[2]);
                float2 t3 = __half22float2(*(__half2*)&pa_h[3]);
                pa_l[0] = pack_h2(c00 - t0.x, c01 - t0.y);
                pa_l[1] = pack_h2(c02 - t1.x, c03 - t1.y);
                pa_l[2] = pack_h2(c10 - t2.x, c11 - t2.y);
                pa_l[3] = pack_h2(c12 - t3.x, c13 - t3.y);
            }

#pragma unroll
            for (int jo = 0; jo < 8; jo += 2) {
                uint32_t bh[4];
                LDSM_X4_T(bh, smaddr(&sV[(k0 + kt_off) * 72 + jo * 8 + nt_off]));
                MMA_F16(acc2[jo],     pa_h, bh);
                MMA_F16(acc2[jo],     pa_l, bh);
                MMA_F16(acc2[jo + 1], pa_h, bh + 2);
                MMA_F16(acc2[jo + 1], pa_l, bh + 2);
            }
        }
    }

    // ---- cross-warp k-reduction + store ----
    __syncthreads();
    if (wn == 0) {
#pragma unroll
        for (int jo = 0; jo < 8; jo++) {
            *(float2*)&sOut[(wm * 16 + qr)     * 72 + jo * 8 + qc] =
                make_float2(acc2[jo][0], acc2[jo][1]);
            *(float2*)&sOut[(wm * 16 + qr + 8) * 72 + jo * 8 + qc] =
                make_float2(acc2[jo][2], acc2[jo][3]);
        }
    }
    __syncthreads();
    if (wn == 1) {
        const int trow0 = base_row + wm * 16 + qr;
#pragma unroll
        for (int jo = 0; jo < 8; jo++) {
            float2 p0 = *(float2*)&sOut[(wm * 16 + qr)     * 72 + jo * 8 + qc];
            float2 p1 = *(float2*)&sOut[(wm * 16 + qr + 8) * 72 + jo * 8 + qc];
            *(float2*)&out[(size_t)trow0 * NH + jo * 8 + qc] =
                make_float2(acc2[jo][0] + p0.x, acc2[jo][1] + p0.y);
            *(float2*)&out[(size_t)(trow0 + 8) * NH + jo * 8 + qc] =
                make_float2(acc2[jo][2] + p1.x, acc2[jo][3] + p1.y);
        }
    }
}

__global__ __launch_bounds__(256, 2) void attn_kernel(const float* __restrict__ x,
                                                      float* __restrict__ out)
{
    // heavy-first 1D order: bid 0-511 -> tb=3 (SLIM=256), ..., 1536-2047 -> tb=0
    const int bid = blockIdx.x;
    const int tb  = 3 - (bid >> 9);
    const int b   = bid & 511;
    if (tb == 3)      attn_body<256>(x, out, b, 3);
    else if (tb == 2) attn_body<192>(x, out, b, 2);
    else if (tb == 1) attn_body<128>(x, out, b, 1);
    else              attn_body<64 >(x, out, b, 0);
}

extern "C" void kernel_launch(void* const* d_in, const int* in_sizes, int n_in,
                              void* d_out, int out_size)
{
    (void)in_sizes; (void)n_in; (void)out_size;
    const float* x   = (const float*)d_in[0];
    const float* Wq  = (const float*)d_in[1];
    const float* Wk  = (const float*)d_in[2];
    const float* Wv  = (const float*)d_in[3];
    const float* Wql = (const float*)d_in[4];
    const float* Wkl = (const float*)d_in[5];
    float* out = (float*)d_out;

    cudaFuncSetAttribute((const void*)attn_kernel,
                         cudaFuncAttributeMaxDynamicSharedMemorySize, ATTN_SMEM_BYTES);
    cudaFuncSetAttribute((const void*)vproj_kernel,
                         cudaFuncAttributeMaxDynamicSharedMemorySize, VPROJ_SMEM);

    convert_wv_kernel<<<(64 * 384 + 255) / 256, 256>>>(Wv);
    wu_kernel<<<384, 256>>>(Wq, Wk, Wql, Wkl);
    vproj_kernel<<<NM / 256, 256, VPROJ_SMEM>>>(x);

    attn_kernel<<<2048, 256, ATTN_SMEM_BYTES>>>(x, out);
}

// round 10
// speedup vs baseline: 2.6587x; 1.1792x over previous
#include <cuda_runtime.h>
#include <cuda_fp16.h>
#include <math.h>
#include <stdint.h>

#define NB 512
#define NT 256
#define NC 384
#define NH 64
#define NS 256
#define NM (NB*NT)   // 131072 rows

// scratch (device globals: allocation-guard safe)
__device__ __align__(16) __half g_v[NM * 64];     // v fp16 [row][64]
__device__ __align__(16) __half g_wv[64 * 384];   // Wv [n][k] K-major fp16
__device__ __align__(16) __half g_wu[384 * 256];  // Wu = Wq@Wql + Wk@Wkl, [k][s] fp16

// ---------------- mma.sync / cp.async helpers (baseline PTX ISA) ----------------
#define LDSM_X4(r, addr)                                                        \
    asm volatile("ldmatrix.sync.aligned.m8n8.x4.shared.b16 {%0,%1,%2,%3}, [%4];" \
        : "=r"((r)[0]), "=r"((r)[1]), "=r"((r)[2]), "=r"((r)[3]) : "r"(addr))

#define LDSM_X4_T(r, addr)                                                      \
    asm volatile("ldmatrix.sync.aligned.m8n8.x4.trans.shared.b16 {%0,%1,%2,%3}, [%4];" \
        : "=r"((r)[0]), "=r"((r)[1]), "=r"((r)[2]), "=r"((r)[3]) : "r"(addr))

#define MMA_F16(d, a, b)                                                        \
    asm volatile("mma.sync.aligned.m16n8k16.row.col.f32.f16.f16.f32 "           \
        "{%0,%1,%2,%3}, {%4,%5,%6,%7}, {%8,%9}, {%0,%1,%2,%3};"                 \
        : "+f"((d)[0]), "+f"((d)[1]), "+f"((d)[2]), "+f"((d)[3])                \
        : "r"((a)[0]), "r"((a)[1]), "r"((a)[2]), "r"((a)[3]),                   \
          "r"((b)[0]), "r"((b)[1]))

#define CP_ASYNC16(dst, src)                                                    \
    asm volatile("cp.async.cg.shared.global [%0], [%1], 16;"                    \
        :: "r"(dst), "l"(src))
#define CP_COMMIT  asm volatile("cp.async.commit_group;" ::: "memory")
#define CP_WAIT0   asm volatile("cp.async.wait_group 0;" ::: "memory")
#define CP_WAIT1   asm volatile("cp.async.wait_group 1;" ::: "memory")

static __device__ __forceinline__ uint32_t pack_h2(float a, float b) {
    __half2 t = __floats2half2_rn(a, b);
    return *(uint32_t*)&t;
}
static __device__ __forceinline__ uint32_t smaddr(const void* p) {
    return (uint32_t)__cvta_generic_to_shared(p);
}
static __device__ __forceinline__ float tanh_fast(float v) {
    float y;
    asm("tanh.approx.f32 %0, %1;" : "=f"(y) : "f"(v));
    return y;
}

// ---------------- Wu = Wq@Wql + Wk@Wkl  (fp32, then fp16) ----------------
__global__ __launch_bounds__(256) void wu_kernel(
    const float* __restrict__ Wq, const float* __restrict__ Wk,
    const float* __restrict__ Wql, const float* __restrict__ Wkl)
{
    __shared__ float qr_[64], kr_[64];
    const int c = blockIdx.x;
    const int s = threadIdx.x;
    if (s < 64)       qr_[s]      = Wq[c * 64 + s];
    else if (s < 128) kr_[s - 64] = Wk[c * 64 + s - 64];
    __syncthreads();
    float acc = 0.f;
#pragma unroll 8
    for (int h = 0; h < 64; h++)
        acc = fmaf(qr_[h], Wql[h * 256 + s], fmaf(kr_[h], Wkl[h * 256 + s], acc));
    g_wu[c * 256 + s] = __float2half_rn(acc);
}

// ---------------- Wv -> fp16 (K-major) ----------------
__global__ __launch_bounds__(256) void convert_wv_kernel(const float* __restrict__ Wv)
{
    const int idx = blockIdx.x * 256 + threadIdx.x;
    if (idx >= 64 * 384) return;
    const int n = idx / 384, k = idx % 384;
    g_wv[idx] = __float2half_rn(Wv[k * 64 + n]);
}

// ---------------- Kernel A: v projection (single fp16) ----------------
#define VPROJ_SMEM ((256*40 + 64*40) * 2)

__global__ __launch_bounds__(256) void vproj_kernel(const float* __restrict__ x)
{
    extern __shared__ __half smv[];
    __half* sXH = smv;               // [256][40]
    __half* sWH = sXH + 256 * 40;    // [64][40]

    const int tid  = threadIdx.x;
    const int lane = tid & 31;
    const int w    = tid >> 5;
    const int wm   = w & 3;
    const int wn   = w >> 2;
    const int m0   = blockIdx.x * 256;

    const int a_row = (lane & 7) + ((lane >> 3) & 1) * 8;
    const int a_col = (lane >> 4) * 8;
    const int b_row = ((lane >> 4) * 8) + (lane & 7);
    const int b_k8  = ((lane >> 3) & 1) * 8;
    const int qr    = lane >> 2;
    const int qc    = (lane & 3) * 2;

    float acc[4][4][4];
#pragma unroll
    for (int mi = 0; mi < 4; mi++)
#pragma unroll
        for (int ni = 0; ni < 4; ni++)
#pragma unroll
            for (int q = 0; q < 4; q++) acc[mi][ni][q] = 0.f;

    for (int c = 0; c < 12; c++) {
        const int kc = c * 32;
        __syncthreads();
#pragma unroll
        for (int i = 0; i < 8; i++) {
            int idx = tid + 256 * i;
            int row = idx >> 3, seg = idx & 7;
            float4 v = *(const float4*)&x[(size_t)(m0 + row) * NC + kc + seg * 4];
            __half h[4];
            h[0] = __float2half_rn(v.x); h[1] = __float2half_rn(v.y);
            h[2] = __float2half_rn(v.z); h[3] = __float2half_rn(v.w);
            *(uint2*)&sXH[row * 40 + seg * 4] = *(uint2*)h;
        }
        if (tid < 128) {
            int row = tid >> 1, seg = tid & 1;
            *(uint4*)&sWH[row * 40 + seg * 16] =
                *(const uint4*)&g_wv[(size_t)row * NC + kc + seg * 16];
            *(uint4*)&sWH[row * 40 + seg * 16 + 8] =
                *(const uint4*)&g_wv[(size_t)row * NC + kc + seg * 16 + 8];
        }
        __syncthreads();

#pragma unroll
        for (int kk = 0; kk < 2; kk++) {
            const int k0 = kk * 16;
            uint32_t ah[4][4];
#pragma unroll
            for (int mi = 0; mi < 4; mi++)
                LDSM_X4(ah[mi], smaddr(&sXH[(wm * 64 + mi * 16 + a_row) * 40 + k0 + a_col]));
#pragma unroll
            for (int ni = 0; ni < 4; ni += 2) {
                uint32_t bh[4];
                LDSM_X4(bh, smaddr(&sWH[(wn * 32 + ni * 8 + b_row) * 40 + k0 + b_k8]));
#pragma unroll
                for (int mi = 0; mi < 4; mi++) {
                    MMA_F16(acc[mi][ni],     ah[mi], bh);
                    MMA_F16(acc[mi][ni + 1], ah[mi], bh + 2);
                }
            }
        }
    }

#pragma unroll
    for (int mi = 0; mi < 4; mi++) {
        int r0 = m0 + wm * 64 + mi * 16 + qr;
#pragma unroll
        for (int ni = 0; ni < 4; ni++) {
            int col = wn * 32 + ni * 8 + qc;
            *(uint32_t*)&g_v[(size_t)r0 * 64 + col]       = pack_h2(acc[mi][ni][0], acc[mi][ni][1]);
            *(uint32_t*)&g_v[(size_t)(r0 + 8) * 64 + col] = pack_h2(acc[mi][ni][2], acc[mi][ni][3]);
        }
    }
}

// ---------------- Kernel B: fused u-GEMM + softmax + p@v (single fp16) ----------------
// 3-stage cp.async pipeline; v overlays phase-1; causal tile-skip. 65KB, 2 CTAs/SM.
#define ATTN_SMEM_BYTES 66560

template <int SLIM>
__device__ __forceinline__ void attn_body(const float* __restrict__ x,
                                          float* __restrict__ out, int b, int tb)
{
    constexpr int SLIMP = SLIM + 8;
    constexpr int NTW   = SLIM / 16;
    constexpr int KW    = SLIM / 2;
    constexpr int XBUF  = 64 * 40;      // halves per x buffer

    extern __shared__ char smraw[];
    // phase 1 (3-stage)
    __half* sXH = (__half*)smraw;            // [3][64][40]  = 15360 B
    __half* sWH = sXH + 3 * XBUF;            // [3][32][SLIMP] = 50688 B
    // phase 2 (overlays phase 1)
    __half* sV  = (__half*)smraw;            // [SLIM][72]  <= 36864 B
    float* sOut    = (float*)smraw;          // [64][72]    = 18432 B, after v dead
    float* rowsumS = (float*)(smraw + 66048);// [2][64]

    const int tid  = threadIdx.x;
    const int lane = tid & 31;
    const int w    = tid >> 5;
    const int wm   = w >> 1;
    const int wn   = w & 1;

    const int a_row  = (lane & 7) + ((lane >> 3) & 1) * 8;
    const int a_col  = (lane >> 4) * 8;
    const int kt_off = (lane & 7) | (((lane >> 3) & 1) << 3);
    const int nt_off = (lane >> 4) * 8;
    const int qr     = lane >> 2;
    const int qc     = (lane & 3) * 2;
    const int base_row = b * NT + tb * 64;

    // causal limit for this warp's row range (max t index)
    const int limit = tb * 64 + wm * 16 + 15;
    const int nw0   = wn * KW;

    auto stageX = [&](int c, int buf) {
        const int kc = c * 32;
#pragma unroll
        for (int i = 0; i < 2; i++) {
            int idx = tid + 256 * i;
            int row = idx >> 3, seg = idx & 7;
            float4 v = *(const float4*)&x[(size_t)(base_row + row) * NC + kc + seg * 4];
            __half h[4];
            h[0] = __float2half_rn(v.x); h[1] = __float2half_rn(v.y);
            h[2] = __float2half_rn(v.z); h[3] = __float2half_rn(v.w);
            *(uint2*)&sXH[buf * XBUF + row * 40 + seg * 4] = *(uint2*)h;
        }
    };
    auto stageW = [&](int c, int buf) {      // cp.async 16B fp16 copies
        const int kc = c * 32;
        for (int L = tid; L < 4 * SLIM; L += 256) {
            int r = L / (SLIM / 8), cs = L % (SLIM / 8);
            CP_ASYNC16(smaddr(&sWH[(buf * 32 + r) * SLIMP + cs * 8]),
                       &g_wu[(size_t)(kc + r) * 256 + cs * 8]);
        }
    };

    // prologue: stages 0,1
    stageW(0, 0); CP_COMMIT; stageX(0, 0);
    stageW(1, 1); CP_COMMIT; stageX(1, 1);

    // ---- GEMM1: u = x @ Wu, K=384, 12 chunks, 3-stage pipeline ----
    float acc[NTW][4];
#pragma unroll
    for (int j = 0; j < NTW; j++)
#pragma unroll
        for (int q = 0; q < 4; q++) acc[j][q] = 0.f;

    for (int c = 0; c < 12; c++) {
        if (c == 11) { CP_WAIT0; } else { CP_WAIT1; }
        __syncthreads();
        if (c + 2 < 12) {
            stageW(c + 2, (c + 2) % 3);
            CP_COMMIT;
            stageX(c + 2, (c + 2) % 3);
        }
        const int buf = c % 3;
#pragma unroll
        for (int kk = 0; kk < 2; kk++) {
            uint32_t ah[4];
            LDSM_X4(ah, smaddr(&sXH[buf * XBUF + (wm * 16 + a_row) * 40 + kk * 16 + a_col]));
#pragma unroll
            for (int j = 0; j < NTW; j += 2) {
                const int n0 = nw0 + j * 8;
                if (n0 <= limit) {   // warp-uniform causal tile-pair skip
                    uint32_t bh[4];
                    LDSM_X4_T(bh, smaddr(&sWH[(buf * 32 + kk * 16 + kt_off) * SLIMP + n0 + nt_off]));
                    MMA_F16(acc[j],     ah, bh);
                    MMA_F16(acc[j + 1], ah, bh + 2);
                }
            }
        }
    }
    __syncthreads();   // all reads of phase-1 buffers done before v overlay

    // ---- v staging into dead phase-1 region, overlapped with softmax ----
    for (int L = tid; L < SLIM * 8; L += 256) {
        int s = L >> 3, seg = L & 7;
        CP_ASYNC16(smaddr(&sV[s * 72 + seg * 8]),
                   &g_v[(size_t)(b * NT + s) * 64 + seg * 8]);
    }
    CP_COMMIT;

    // ---- tanh + causal mask + exp + row sums (tanh bounded: no max pass) ----
    const int tg0 = tb * 64 + wm * 16 + qr;
    float rsum0 = 0.f, rsum1 = 0.f;
#pragma unroll
    for (int j = 0; j < NTW; j++) {
        const int c0 = nw0 + j * 8 + qc;
        if (nw0 + j * 8 <= limit) {
            float v0 = (c0     <= tg0    ) ? __expf(tanh_fast(acc[j][0])) : 0.f;
            float v1 = (c0 + 1 <= tg0    ) ? __expf(tanh_fast(acc[j][1])) : 0.f;
            float v2 = (c0     <= tg0 + 8) ? __expf(tanh_fast(acc[j][2])) : 0.f;
            float v3 = (c0 + 1 <= tg0 + 8) ? __expf(tanh_fast(acc[j][3])) : 0.f;
            acc[j][0] = v0; acc[j][1] = v1; acc[j][2] = v2; acc[j][3] = v3;
            rsum0 += v0 + v1;
            rsum1 += v2 + v3;
        } else {
            acc[j][0] = 0.f; acc[j][1] = 0.f; acc[j][2] = 0.f; acc[j][3] = 0.f;
        }
    }
#pragma unroll
    for (int off = 1; off <= 2; off <<= 1) {
        rsum0 += __shfl_xor_sync(0xffffffffu, rsum0, off);
        rsum1 += __shfl_xor_sync(0xffffffffu, rsum1, off);
    }
    if ((lane & 3) == 0) {
        rowsumS[wn * 64 + wm * 16 + qr]     = rsum0;
        rowsumS[wn * 64 + wm * 16 + qr + 8] = rsum1;
    }
    __syncthreads();
    const float inv0 = 1.f / (rowsumS[wm * 16 + qr]     + rowsumS[64 + wm * 16 + qr]);
    const float inv1 = 1.f / (rowsumS[wm * 16 + qr + 8] + rowsumS[64 + wm * 16 + qr + 8]);

    CP_WAIT0;
    __syncthreads();

    // ---- GEMM2: out += p @ v over k in [wn*KW, wn*KW+KW); p single fp16 ----
    float acc2[8][4];
#pragma unroll
    for (int jo = 0; jo < 8; jo++)
#pragma unroll
        for (int q = 0; q < 4; q++) acc2[jo][q] = 0.f;

#pragma unroll
    for (int jp = 0; jp < NTW / 2; jp++) {
        const int k0 = nw0 + jp * 16;
        if (k0 <= limit) {   // warp-uniform causal k-pair skip
            uint32_t pa_h[4];
            pa_h[0] = pack_h2(acc[2*jp][0]   * inv0, acc[2*jp][1]   * inv0);
            pa_h[1] = pack_h2(acc[2*jp][2]   * inv1, acc[2*jp][3]   * inv1);
            pa_h[2] = pack_h2(acc[2*jp+1][0] * inv0, acc[2*jp+1][1] * inv0);
            pa_h[3] = pack_h2(acc[2*jp+1][2] * inv1, acc[2*jp+1][3] * inv1);

#pragma unroll
            for (int jo = 0; jo < 8; jo += 2) {
                uint32_t bh[4];
                LDSM_X4_T(bh, smaddr(&sV[(k0 + kt_off) * 72 + jo * 8 + nt_off]));
                MMA_F16(acc2[jo],     pa_h, bh);
                MMA_F16(acc2[jo + 1], pa_h, bh + 2);
            }
        }
    }

    // ---- cross-warp k-reduction + store ----
    __syncthreads();
    if (wn == 0) {
#pragma unroll
        for (int jo = 0; jo < 8; jo++) {
            *(float2*)&sOut[(wm * 16 + qr)     * 72 + jo * 8 + qc] =
                make_float2(acc2[jo][0], acc2[jo][1]);
            *(float2*)&sOut[(wm * 16 + qr + 8) * 72 + jo * 8 + qc] =
                make_float2(acc2[jo][2], acc2[jo][3]);
        }
    }
    __syncthreads();
    if (wn == 1) {
        const int trow0 = base_row + wm * 16 + qr;
#pragma unroll
        for (int jo = 0; jo < 8; jo++) {
            float2 p0 = *(float2*)&sOut[(wm * 16 + qr)     * 72 + jo * 8 + qc];
            float2 p1 = *(float2*)&sOut[(wm * 16 + qr + 8) * 72 + jo * 8 + qc];
            *(float2*)&out[(size_t)trow0 * NH + jo * 8 + qc] =
                make_float2(acc2[jo][0] + p0.x, acc2[jo][1] + p0.y);
            *(float2*)&out[(size_t)(trow0 + 8) * NH + jo * 8 + qc] =
                make_float2(acc2[jo][2] + p1.x, acc2[jo][3] + p1.y);
        }
    }
}

__global__ __launch_bounds__(256, 2) void attn_kernel(const float* __restrict__ x,
                                                      float* __restrict__ out)
{
    // heavy-first 1D order: bid 0-511 -> tb=3 (SLIM=256), ..., 1536-2047 -> tb=0
    const int bid = blockIdx.x;
    const int tb  = 3 - (bid >> 9);
    const int b   = bid & 511;
    if (tb == 3)      attn_body<256>(x, out, b, 3);
    else if (tb == 2) attn_body<192>(x, out, b, 2);
    else if (tb == 1) attn_body<128>(x, out, b, 1);
    else              attn_body<64 >(x, out, b, 0);
}

extern "C" void kernel_launch(void* const* d_in, const int* in_sizes, int n_in,
                              void* d_out, int out_size)
{
    (void)in_sizes; (void)n_in; (void)out_size;
    const float* x   = (const float*)d_in[0];
    const float* Wq  = (const float*)d_in[1];
    const float* Wk  = (const float*)d_in[2];
    const float* Wv  = (const float*)d_in[3];
    const float* Wql = (const float*)d_in[4];
    const float* Wkl = (const float*)d_in[5];
    float* out = (float*)d_out;

    cudaFuncSetAttribute((const void*)attn_kernel,
                         cudaFuncAttributeMaxDynamicSharedMemorySize, ATTN_SMEM_BYTES);
    cudaFuncSetAttribute((const void*)vproj_kernel,
                         cudaFuncAttributeMaxDynamicSharedMemorySize, VPROJ_SMEM);

    convert_wv_kernel<<<(64 * 384 + 255) / 256, 256>>>(Wv);
    wu_kernel<<<384, 256>>>(Wq, Wk, Wql, Wkl);
    vproj_kernel<<<NM / 256, 256, VPROJ_SMEM>>>(x);

    attn_kernel<<<2048, 256, ATTN_SMEM_BYTES>>>(x, out);
}

// round 11
// speedup vs baseline: 2.9822x; 1.1216x over previous
#include <cuda_runtime.h>
#include <cuda_fp16.h>
#include <math.h>
#include <stdint.h>

#define NB 512
#define NT 256
#define NC 384
#define NH 64
#define NS 256
#define NM (NB*NT)   // 131072 rows

// scratch (device globals: allocation-guard safe)
__device__ __align__(16) __half g_xh[NM * NC];    // x fp16 [row][384] (written by vproj)
__device__ __align__(16) __half g_v[NM * 64];     // v fp16 [row][64]
__device__ __align__(16) __half g_wv[64 * 384];   // Wv [n][k] K-major fp16
__device__ __align__(16) __half g_wu[384 * 256];  // Wu = Wq@Wql + Wk@Wkl, [k][s] fp16

// ---------------- mma.sync / cp.async helpers (baseline PTX ISA) ----------------
#define LDSM_X4(r, addr)                                                        \
    asm volatile("ldmatrix.sync.aligned.m8n8.x4.shared.b16 {%0,%1,%2,%3}, [%4];" \
        : "=r"((r)[0]), "=r"((r)[1]), "=r"((r)[2]), "=r"((r)[3]) : "r"(addr))

#define LDSM_X4_T(r, addr)                                                      \
    asm volatile("ldmatrix.sync.aligned.m8n8.x4.trans.shared.b16 {%0,%1,%2,%3}, [%4];" \
        : "=r"((r)[0]), "=r"((r)[1]), "=r"((r)[2]), "=r"((r)[3]) : "r"(addr))

#define MMA_F16(d, a, b)                                                        \
    asm volatile("mma.sync.aligned.m16n8k16.row.col.f32.f16.f16.f32 "           \
        "{%0,%1,%2,%3}, {%4,%5,%6,%7}, {%8,%9}, {%0,%1,%2,%3};"                 \
        : "+f"((d)[0]), "+f"((d)[1]), "+f"((d)[2]), "+f"((d)[3])                \
        : "r"((a)[0]), "r"((a)[1]), "r"((a)[2]), "r"((a)[3]),                   \
          "r"((b)[0]), "r"((b)[1]))

#define CP_ASYNC16(dst, src)                                                    \
    asm volatile("cp.async.cg.shared.global [%0], [%1], 16;"                    \
        :: "r"(dst), "l"(src))
#define CP_COMMIT  asm volatile("cp.async.commit_group;" ::: "memory")
#define CP_WAIT0   asm volatile("cp.async.wait_group 0;" ::: "memory")
#define CP_WAIT1   asm volatile("cp.async.wait_group 1;" ::: "memory")

static __device__ __forceinline__ uint32_t pack_h2(float a, float b) {
    __half2 t = __floats2half2_rn(a, b);
    return *(uint32_t*)&t;
}
static __device__ __forceinline__ uint32_t smaddr(const void* p) {
    return (uint32_t)__cvta_generic_to_shared(p);
}
static __device__ __forceinline__ float tanh_fast(float v) {
    float y;
    asm("tanh.approx.f32 %0, %1;" : "=f"(y) : "f"(v));
    return y;
}

// ---------------- Wu = Wq@Wql + Wk@Wkl  (fp32, then fp16) ----------------
__global__ __launch_bounds__(256) void wu_kernel(
    const float* __restrict__ Wq, const float* __restrict__ Wk,
    const float* __restrict__ Wql, const float* __restrict__ Wkl)
{
    __shared__ float qr_[64], kr_[64];
    const int c = blockIdx.x;
    const int s = threadIdx.x;
    if (s < 64)       qr_[s]      = Wq[c * 64 + s];
    else if (s < 128) kr_[s - 64] = Wk[c * 64 + s - 64];
    __syncthreads();
    float acc = 0.f;
#pragma unroll 8
    for (int h = 0; h < 64; h++)
        acc = fmaf(qr_[h], Wql[h * 256 + s], fmaf(kr_[h], Wkl[h * 256 + s], acc));
    g_wu[c * 256 + s] = __float2half_rn(acc);
}

// ---------------- Wv -> fp16 (K-major) ----------------
__global__ __launch_bounds__(256) void convert_wv_kernel(const float* __restrict__ Wv)
{
    const int idx = blockIdx.x * 256 + threadIdx.x;
    if (idx >= 64 * 384) return;
    const int n = idx / 384, k = idx % 384;
    g_wv[idx] = __float2half_rn(Wv[k * 64 + n]);
}

// ---------------- Kernel A: v projection + x fp16 export ----------------
#define VPROJ_SMEM ((256*40 + 64*40) * 2)

__global__ __launch_bounds__(256) void vproj_kernel(const float* __restrict__ x)
{
    extern __shared__ __half smv[];
    __half* sXH = smv;               // [256][40]
    __half* sWH = sXH + 256 * 40;    // [64][40]

    const int tid  = threadIdx.x;
    const int lane = tid & 31;
    const int w    = tid >> 5;
    const int wm   = w & 3;
    const int wn   = w >> 2;
    const int m0   = blockIdx.x * 256;

    const int a_row = (lane & 7) + ((lane >> 3) & 1) * 8;
    const int a_col = (lane >> 4) * 8;
    const int b_row = ((lane >> 4) * 8) + (lane & 7);
    const int b_k8  = ((lane >> 3) & 1) * 8;
    const int qr    = lane >> 2;
    const int qc    = (lane & 3) * 2;

    float acc[4][4][4];
#pragma unroll
    for (int mi = 0; mi < 4; mi++)
#pragma unroll
        for (int ni = 0; ni < 4; ni++)
#pragma unroll
            for (int q = 0; q < 4; q++) acc[mi][ni][q] = 0.f;

    for (int c = 0; c < 12; c++) {
        const int kc = c * 32;
        __syncthreads();
#pragma unroll
        for (int i = 0; i < 8; i++) {
            int idx = tid + 256 * i;
            int row = idx >> 3, seg = idx & 7;
            float4 v = *(const float4*)&x[(size_t)(m0 + row) * NC + kc + seg * 4];
            __half h[4];
            h[0] = __float2half_rn(v.x); h[1] = __float2half_rn(v.y);
            h[2] = __float2half_rn(v.z); h[3] = __float2half_rn(v.w);
            *(uint2*)&sXH[row * 40 + seg * 4] = *(uint2*)h;
            // export x fp16 (bitwise same rounding attn used inline before)
            *(uint2*)&g_xh[(size_t)(m0 + row) * NC + kc + seg * 4] = *(uint2*)h;
        }
        if (tid < 128) {
            int row = tid >> 1, seg = tid & 1;
            *(uint4*)&sWH[row * 40 + seg * 16] =
                *(const uint4*)&g_wv[(size_t)row * NC + kc + seg * 16];
            *(uint4*)&sWH[row * 40 + seg * 16 + 8] =
                *(const uint4*)&g_wv[(size_t)row * NC + kc + seg * 16 + 8];
        }
        __syncthreads();

#pragma unroll
        for (int kk = 0; kk < 2; kk++) {
            const int k0 = kk * 16;
            uint32_t ah[4][4];
#pragma unroll
            for (int mi = 0; mi < 4; mi++)
                LDSM_X4(ah[mi], smaddr(&sXH[(wm * 64 + mi * 16 + a_row) * 40 + k0 + a_col]));
#pragma unroll
            for (int ni = 0; ni < 4; ni += 2) {
                uint32_t bh[4];
                LDSM_X4(bh, smaddr(&sWH[(wn * 32 + ni * 8 + b_row) * 40 + k0 + b_k8]));
#pragma unroll
                for (int mi = 0; mi < 4; mi++) {
                    MMA_F16(acc[mi][ni],     ah[mi], bh);
                    MMA_F16(acc[mi][ni + 1], ah[mi], bh + 2);
                }
            }
        }
    }

#pragma unroll
    for (int mi = 0; mi < 4; mi++) {
        int r0 = m0 + wm * 64 + mi * 16 + qr;
#pragma unroll
        for (int ni = 0; ni < 4; ni++) {
            int col = wn * 32 + ni * 8 + qc;
            *(uint32_t*)&g_v[(size_t)r0 * 64 + col]       = pack_h2(acc[mi][ni][0], acc[mi][ni][1]);
            *(uint32_t*)&g_v[(size_t)(r0 + 8) * 64 + col] = pack_h2(acc[mi][ni][2], acc[mi][ni][3]);
        }
    }
}

// ---------------- Kernel B: fused u-GEMM + softmax + p@v (pure cp.async producer) ----------------
#define ATTN_SMEM_BYTES 66560

template <int SLIM>
__device__ __forceinline__ void attn_body(float* __restrict__ out, int b, int tb)
{
    constexpr int SLIMP = SLIM + 8;
    constexpr int NTW   = SLIM / 16;
    constexpr int KW    = SLIM / 2;
    constexpr int XBUF  = 64 * 40;      // halves per x buffer

    extern __shared__ char smraw[];
    // phase 1 (3-stage)
    __half* sXH = (__half*)smraw;            // [3][64][40]  = 15360 B
    __half* sWH = sXH + 3 * XBUF;            // [3][32][SLIMP]
    // phase 2 (overlays phase 1)
    __half* sV  = (__half*)smraw;            // [SLIM][72]
    float* sOut    = (float*)smraw;          // [64][72], after v dead
    float* rowsumS = (float*)(smraw + 66048);// [2][64]

    const int tid  = threadIdx.x;
    const int lane = tid & 31;
    const int w    = tid >> 5;
    const int wm   = w >> 1;
    const int wn   = w & 1;

    const int a_row  = (lane & 7) + ((lane >> 3) & 1) * 8;
    const int a_col  = (lane >> 4) * 8;
    const int kt_off = (lane & 7) | (((lane >> 3) & 1) << 3);
    const int nt_off = (lane >> 4) * 8;
    const int qr     = lane >> 2;
    const int qc     = (lane & 3) * 2;
    const int base_row = b * NT + tb * 64;

    const int limit = tb * 64 + wm * 16 + 15;
    const int nw0   = wn * KW;

    const int xrow = tid >> 2, xq = tid & 3;  // stageX addressing
    auto stageX = [&](int c, int buf) {       // 1 cp.async/thread: 64 rows x 32 k
        CP_ASYNC16(smaddr(&sXH[buf * XBUF + xrow * 40 + xq * 8]),
                   &g_xh[(size_t)(base_row + xrow) * NC + c * 32 + xq * 8]);
    };
    auto stageW = [&](int c, int buf) {
        const int kc = c * 32;
        for (int L = tid; L < 4 * SLIM; L += 256) {
            int r = L / (SLIM / 8), cs = L % (SLIM / 8);
            CP_ASYNC16(smaddr(&sWH[(buf * 32 + r) * SLIMP + cs * 8]),
                       &g_wu[(size_t)(kc + r) * 256 + cs * 8]);
        }
    };

    // prologue: stages 0,1 (W + x in one group per stage)
    stageW(0, 0); stageX(0, 0); CP_COMMIT;
    stageW(1, 1); stageX(1, 1); CP_COMMIT;

    // ---- GEMM1: u = x @ Wu, K=384, 12 chunks, 3-stage pipeline ----
    float acc[NTW][4];
#pragma unroll
    for (int j = 0; j < NTW; j++)
#pragma unroll
        for (int q = 0; q < 4; q++) acc[j][q] = 0.f;

    for (int c = 0; c < 12; c++) {
        if (c == 11) { CP_WAIT0; } else { CP_WAIT1; }
        __syncthreads();
        if (c + 2 < 12) {
            stageW(c + 2, (c + 2) % 3);
            stageX(c + 2, (c + 2) % 3);
            CP_COMMIT;
        }
        const int buf = c % 3;
#pragma unroll
        for (int kk = 0; kk < 2; kk++) {
            uint32_t ah[4];
            LDSM_X4(ah, smaddr(&sXH[buf * XBUF + (wm * 16 + a_row) * 40 + kk * 16 + a_col]));
#pragma unroll
            for (int j = 0; j < NTW; j += 2) {
                const int n0 = nw0 + j * 8;
                if (n0 <= limit) {   // warp-uniform causal tile-pair skip
                    uint32_t bh[4];
                    LDSM_X4_T(bh, smaddr(&sWH[(buf * 32 + kk * 16 + kt_off) * SLIMP + n0 + nt_off]));
                    MMA_F16(acc[j],     ah, bh);
                    MMA_F16(acc[j + 1], ah, bh + 2);
                }
            }
        }
    }
    __syncthreads();   // all reads of phase-1 buffers done before v overlay

    // ---- v staging into dead phase-1 region, overlapped with softmax ----
    for (int L = tid; L < SLIM * 8; L += 256) {
        int s = L >> 3, seg = L & 7;
        CP_ASYNC16(smaddr(&sV[s * 72 + seg * 8]),
                   &g_v[(size_t)(b * NT + s) * 64 + seg * 8]);
    }
    CP_COMMIT;

    // ---- tanh + causal mask + exp + row sums (tanh bounded: no max pass) ----
    const int tg0 = tb * 64 + wm * 16 + qr;
    float rsum0 = 0.f, rsum1 = 0.f;
#pragma unroll
    for (int j = 0; j < NTW; j++) {
        const int c0 = nw0 + j * 8 + qc;
        if (nw0 + j * 8 <= limit) {   // skipped tiles already zero from init
            float v0 = (c0     <= tg0    ) ? __expf(tanh_fast(acc[j][0])) : 0.f;
            float v1 = (c0 + 1 <= tg0    ) ? __expf(tanh_fast(acc[j][1])) : 0.f;
            float v2 = (c0     <= tg0 + 8) ? __expf(tanh_fast(acc[j][2])) : 0.f;
            float v3 = (c0 + 1 <= tg0 + 8) ? __expf(tanh_fast(acc[j][3])) : 0.f;
            acc[j][0] = v0; acc[j][1] = v1; acc[j][2] = v2; acc[j][3] = v3;
            rsum0 += v0 + v1;
            rsum1 += v2 + v3;
        }
    }
#pragma unroll
    for (int off = 1; off <= 2; off <<= 1) {
        rsum0 += __shfl_xor_sync(0xffffffffu, rsum0, off);
        rsum1 += __shfl_xor_sync(0xffffffffu, rsum1, off);
    }
    if ((lane & 3) == 0) {
        rowsumS[wn * 64 + wm * 16 + qr]     = rsum0;
        rowsumS[wn * 64 + wm * 16 + qr + 8] = rsum1;
    }
    __syncthreads();
    const float inv0 = 1.f / (rowsumS[wm * 16 + qr]     + rowsumS[64 + wm * 16 + qr]);
    const float inv1 = 1.f / (rowsumS[wm * 16 + qr + 8] + rowsumS[64 + wm * 16 + qr + 8]);

    CP_WAIT0;
    __syncthreads();

    // ---- GEMM2: out += p @ v over k in [wn*KW, wn*KW+KW); p single fp16 ----
    float acc2[8][4];
#pragma unroll
    for (int jo = 0; jo < 8; jo++)
#pragma unroll
        for (int q = 0; q < 4; q++) acc2[jo][q] = 0.f;

#pragma unroll
    for (int jp = 0; jp < NTW / 2; jp++) {
        const int k0 = nw0 + jp * 16;
        if (k0 <= limit) {   // warp-uniform causal k-pair skip
            uint32_t pa_h[4];
            pa_h[0] = pack_h2(acc[2*jp][0]   * inv0, acc[2*jp][1]   * inv0);
            pa_h[1] = pack_h2(acc[2*jp][2]   * inv1, acc[2*jp][3]   * inv1);
            pa_h[2] = pack_h2(acc[2*jp+1][0] * inv0, acc[2*jp+1][1] * inv0);
            pa_h[3] = pack_h2(acc[2*jp+1][2] * inv1, acc[2*jp+1][3] * inv1);

#pragma unroll
            for (int jo = 0; jo < 8; jo += 2) {
                uint32_t bh[4];
                LDSM_X4_T(bh, smaddr(&sV[(k0 + kt_off) * 72 + jo * 8 + nt_off]));
                MMA_F16(acc2[jo],     pa_h, bh);
                MMA_F16(acc2[jo + 1], pa_h, bh + 2);
            }
        }
    }

    // ---- cross-warp k-reduction + store ----
    __syncthreads();
    if (wn == 0) {
#pragma unroll
        for (int jo = 0; jo < 8; jo++) {
            *(float2*)&sOut[(wm * 16 + qr)     * 72 + jo * 8 + qc] =
                make_float2(acc2[jo][0], acc2[jo][1]);
            *(float2*)&sOut[(wm * 16 + qr + 8) * 72 + jo * 8 + qc] =
                make_float2(acc2[jo][2], acc2[jo][3]);
        }
    }
    __syncthreads();
    if (wn == 1) {
        const int trow0 = base_row + wm * 16 + qr;
#pragma unroll
        for (int jo = 0; jo < 8; jo++) {
            float2 p0 = *(float2*)&sOut[(wm * 16 + qr)     * 72 + jo * 8 + qc];
            float2 p1 = *(float2*)&sOut[(wm * 16 + qr + 8) * 72 + jo * 8 + qc];
            *(float2*)&out[(size_t)trow0 * NH + jo * 8 + qc] =
                make_float2(acc2[jo][0] + p0.x, acc2[jo][1] + p0.y);
            *(float2*)&out[(size_t)(trow0 + 8) * NH + jo * 8 + qc] =
                make_float2(acc2[jo][2] + p1.x, acc2[jo][3] + p1.y);
        }
    }
}

__global__ __launch_bounds__(256, 2) void attn_kernel(float* __restrict__ out)
{
    // heavy-first 1D order: bid 0-511 -> tb=3 (SLIM=256), ..., 1536-2047 -> tb=0
    const int bid = blockIdx.x;
    const int tb  = 3 - (bid >> 9);
    const int b   = bid & 511;
    if (tb == 3)      attn_body<256>(out, b, 3);
    else if (tb == 2) attn_body<192>(out, b, 2);
    else if (tb == 1) attn_body<128>(out, b, 1);
    else              attn_body<64 >(out, b, 0);
}

extern "C" void kernel_launch(void* const* d_in, const int* in_sizes, int n_in,
                              void* d_out, int out_size)
{
    (void)in_sizes; (void)n_in; (void)out_size;
    const float* x   = (const float*)d_in[0];
    const float* Wq  = (const float*)d_in[1];
    const float* Wk  = (const float*)d_in[2];
    const float* Wv  = (const float*)d_in[3];
    const float* Wql = (const float*)d_in[4];
    const float* Wkl = (const float*)d_in[5];
    float* out = (float*)d_out;

    cudaFuncSetAttribute((const void*)attn_kernel,
                         cudaFuncAttributeMaxDynamicSharedMemorySize, ATTN_SMEM_BYTES);
    cudaFuncSetAttribute((const void*)vproj_kernel,
                         cudaFuncAttributeMaxDynamicSharedMemorySize, VPROJ_SMEM);

    convert_wv_kernel<<<(64 * 384 + 255) / 256, 256>>>(Wv);
    wu_kernel<<<384, 256>>>(Wq, Wk, Wql, Wkl);
    vproj_kernel<<<NM / 256, 256, VPROJ_SMEM>>>(x);

    attn_kernel<<<2048, 256, ATTN_SMEM_BYTES>>>(out);
}

// round 13
// speedup vs baseline: 3.3469x; 1.1223x over previous
#include <cuda_runtime.h>
#include <cuda_fp16.h>
#include <math.h>
#include <stdint.h>

#define NB 512
#define NT 256
#define NC 384
#define NH 64
#define NS 256
#define NM (NB*NT)   // 131072 rows

// scratch (device globals: allocation-guard safe)
__device__ __align__(16) __half g_xh[NM * NC];    // x fp16 [row][384] (written by vproj)
__device__ __align__(16) __half g_v[NM * 64];     // v fp16 [row][64]
__device__ __align__(16) __half g_wv[64 * 384];   // Wv [n][k] K-major fp16
__device__ __align__(16) __half g_wu[384 * 256];  // Wu = Wq@Wql + Wk@Wkl, [k][s] fp16

// ---------------- mma.sync / cp.async helpers (baseline PTX ISA) ----------------
#define LDSM_X4(r, addr)                                                        \
    asm volatile("ldmatrix.sync.aligned.m8n8.x4.shared.b16 {%0,%1,%2,%3}, [%4];" \
        : "=r"((r)[0]), "=r"((r)[1]), "=r"((r)[2]), "=r"((r)[3]) : "r"(addr))

#define LDSM_X4_T(r, addr)                                                      \
    asm volatile("ldmatrix.sync.aligned.m8n8.x4.trans.shared.b16 {%0,%1,%2,%3}, [%4];" \
        : "=r"((r)[0]), "=r"((r)[1]), "=r"((r)[2]), "=r"((r)[3]) : "r"(addr))

#define MMA_F16(d, a, b)                                                        \
    asm volatile("mma.sync.aligned.m16n8k16.row.col.f32.f16.f16.f32 "           \
        "{%0,%1,%2,%3}, {%4,%5,%6,%7}, {%8,%9}, {%0,%1,%2,%3};"                 \
        : "+f"((d)[0]), "+f"((d)[1]), "+f"((d)[2]), "+f"((d)[3])                \
        : "r"((a)[0]), "r"((a)[1]), "r"((a)[2]), "r"((a)[3]),                   \
          "r"((b)[0]), "r"((b)[1]))

#define CP_ASYNC16(dst, src)                                                    \
    asm volatile("cp.async.cg.shared.global [%0], [%1], 16;"                    \
        :: "r"(dst), "l"(src))
#define CP_COMMIT  asm volatile("cp.async.commit_group;" ::: "memory")
#define CP_WAIT0   asm volatile("cp.async.wait_group 0;" ::: "memory")
#define CP_WAIT1   asm volatile("cp.async.wait_group 1;" ::: "memory")

static __device__ __forceinline__ uint32_t pack_h2(float a, float b) {
    __half2 t = __floats2half2_rn(a, b);
    return *(uint32_t*)&t;
}
static __device__ __forceinline__ uint32_t smaddr(const void* p) {
    return (uint32_t)__cvta_generic_to_shared(p);
}
static __device__ __forceinline__ float tanh_fast(float v) {
    float y;
    asm("tanh.approx.f32 %0, %1;" : "=f"(y) : "f"(v));
    return y;
}

// ---------------- prep: Wu = Wq@Wql + Wk@Wkl (fp32->fp16) + Wv->fp16 ----------------
__global__ __launch_bounds__(256) void prep_kernel(
    const float* __restrict__ Wq, const float* __restrict__ Wk,
    const float* __restrict__ Wql, const float* __restrict__ Wkl,
    const float* __restrict__ Wv)
{
    __shared__ float qr_[64], kr_[64];
    const int bb = blockIdx.x;
    const int s  = threadIdx.x;
    if (bb < 384) {
        const int c = bb;
        if (s < 64)       qr_[s]      = Wq[c * 64 + s];
        else if (s < 128) kr_[s - 64] = Wk[c * 64 + s - 64];
        __syncthreads();
        float acc = 0.f;
#pragma unroll 8
        for (int h = 0; h < 64; h++)
            acc = fmaf(qr_[h], Wql[h * 256 + s], fmaf(kr_[h], Wkl[h * 256 + s], acc));
        g_wu[c * 256 + s] = __float2half_rn(acc);
    } else {
        const int idx = (bb - 384) * 256 + s;
        if (idx < 64 * 384) {
            const int n = idx / 384, k = idx % 384;
            g_wv[idx] = __float2half_rn(Wv[k * 64 + n]);
        }
    }
}

// ---------------- Kernel A: v projection + x fp16 export ----------------
// Wv fully resident in smem; x register-prefetched; convert+export in chunk tail.
#define VPROJ_SMEM ((64*392 + 256*40) * 2)   // 70656 B

__global__ __launch_bounds__(256, 2) void vproj_kernel(const float* __restrict__ x)
{
    extern __shared__ __half smv[];
    __half* sWv = smv;               // [64][392]  (384 + 8 pad)
    __half* sX  = smv + 64 * 392;    // [256][40]

    const int tid  = threadIdx.x;
    const int lane = tid & 31;
    const int w    = tid >> 5;
    const int wm   = w & 3;
    const int wn   = w >> 2;
    const int m0   = blockIdx.x * 256;

    const int a_row = (lane & 7) + ((lane >> 3) & 1) * 8;
    const int a_col = (lane >> 4) * 8;
    const int b_row = ((lane >> 4) * 8) + (lane & 7);
    const int b_k8  = ((lane >> 3) & 1) * 8;
    const int qr    = lane >> 2;
    const int qc    = (lane & 3) * 2;

    // preload whole Wv: 64 rows x 384 halves = 64 x 48 x 16B copies
    for (int L = tid; L < 3072; L += 256) {
        int n = L / 48, seg = L % 48;                         // FIXED: 48 segs/row
        CP_ASYNC16(smaddr(&sWv[n * 392 + seg * 8]), &g_wv[(size_t)n * NC + seg * 8]);
    }
    CP_COMMIT;

    const int xrow = tid >> 3, xseg = tid & 7;   // 32 rows x 8 segs per pass
    float4 vv[8];
    auto ldgX = [&](int c) {
#pragma unroll
        for (int i = 0; i < 8; i++) {
            int row = xrow + 32 * i;
            vv[i] = *(const float4*)&x[(size_t)(m0 + row) * NC + c * 32 + xseg * 4];
        }
    };
    auto cvtX = [&](int c) {
#pragma unroll
        for (int i = 0; i < 8; i++) {
            int row = xrow + 32 * i;
            __half h[4];
            h[0] = __float2half_rn(vv[i].x); h[1] = __float2half_rn(vv[i].y);
            h[2] = __float2half_rn(vv[i].z); h[3] = __float2half_rn(vv[i].w);
            *(uint2*)&sX[row * 40 + xseg * 4] = *(uint2*)h;
            *(uint2*)&g_xh[(size_t)(m0 + row) * NC + c * 32 + xseg * 4] = *(uint2*)h;
        }
    };

    ldgX(0);
    CP_WAIT0;        // Wv resident
    cvtX(0);
    __syncthreads();

    float acc[4][4][4];
#pragma unroll
    for (int mi = 0; mi < 4; mi++)
#pragma unroll
        for (int ni = 0; ni < 4; ni++)
#pragma unroll
            for (int q = 0; q < 4; q++) acc[mi][ni][q] = 0.f;

    for (int c = 0; c < 12; c++) {
        if (c < 11) ldgX(c + 1);     // prefetch next chunk into regs
#pragma unroll
        for (int kk = 0; kk < 2; kk++) {
            const int kglob = c * 32 + kk * 16;
            uint32_t ah[4][4];
#pragma unroll
            for (int mi = 0; mi < 4; mi++)
                LDSM_X4(ah[mi], smaddr(&sX[(wm * 64 + mi * 16 + a_row) * 40 + kk * 16 + a_col]));
#pragma unroll
            for (int ni = 0; ni < 4; ni += 2) {
                uint32_t bh[4];
                LDSM_X4(bh, smaddr(&sWv[(wn * 32 + ni * 8 + b_row) * 392 + kglob + b_k8]));
#pragma unroll
                for (int mi = 0; mi < 4; mi++) {
                    MMA_F16(acc[mi][ni],     ah[mi], bh);
                    MMA_F16(acc[mi][ni + 1], ah[mi], bh + 2);
                }
            }
        }
        __syncthreads();             // MMA reads of sX done
        if (c < 11) cvtX(c + 1);     // overwrite sX + export
        __syncthreads();             // sX visible
    }

#pragma unroll
    for (int mi = 0; mi < 4; mi++) {
        int r0 = m0 + wm * 64 + mi * 16 + qr;
#pragma unroll
        for (int ni = 0; ni < 4; ni++) {
            int col = wn * 32 + ni * 8 + qc;
            *(uint32_t*)&g_v[(size_t)r0 * 64 + col]       = pack_h2(acc[mi][ni][0], acc[mi][ni][1]);
            *(uint32_t*)&g_v[(size_t)(r0 + 8) * 64 + col] = pack_h2(acc[mi][ni][2], acc[mi][ni][3]);
        }
    }
}

// ---------------- Kernel B: fused u-GEMM + softmax + p@v (pure cp.async producer) ----------------
#define ATTN_SMEM_BYTES 66560

template <int SLIM>
__device__ __forceinline__ void attn_body(float* __restrict__ out, int b, int tb)
{
    constexpr int SLIMP = SLIM + 8;
    constexpr int NTW   = SLIM / 16;
    constexpr int KW    = SLIM / 2;
    constexpr int XBUF  = 64 * 40;      // halves per x buffer

    extern __shared__ char smraw[];
    // phase 1 (3-stage)
    __half* sXH = (__half*)smraw;            // [3][64][40]
    __half* sWH = sXH + 3 * XBUF;            // [3][32][SLIMP]
    // phase 2 (overlays phase 1)
    __half* sV  = (__half*)smraw;            // [SLIM][72]
    float* sOutA   = (float*)smraw;          // [64][72]
    float* sOutB   = sOutA + 64 * 72;        // [64][72]
    float* rowsumS = (float*)(smraw + 66048);// [2][64]

    const int tid  = threadIdx.x;
    const int lane = tid & 31;
    const int w    = tid >> 5;
    const int wm   = w >> 1;
    const int wn   = w & 1;

    const int a_row  = (lane & 7) + ((lane >> 3) & 1) * 8;
    const int a_col  = (lane >> 4) * 8;
    const int kt_off = (lane & 7) | (((lane >> 3) & 1) << 3);
    const int nt_off = (lane >> 4) * 8;
    const int qr     = lane >> 2;
    const int qc     = (lane & 3) * 2;
    const int base_row = b * NT + tb * 64;

    const int limit = tb * 64 + wm * 16 + 15;
    const int nw0   = wn * KW;

    const int xrow = tid >> 2, xq = tid & 3;
    auto stageX = [&](int c, int buf) {
        CP_ASYNC16(smaddr(&sXH[buf * XBUF + xrow * 40 + xq * 8]),
                   &g_xh[(size_t)(base_row + xrow) * NC + c * 32 + xq * 8]);
    };
    auto stageW = [&](int c, int buf) {
        const int kc = c * 32;
        for (int L = tid; L < 4 * SLIM; L += 256) {
            int r = L / (SLIM / 8), cs = L % (SLIM / 8);
            CP_ASYNC16(smaddr(&sWH[(buf * 32 + r) * SLIMP + cs * 8]),
                       &g_wu[(size_t)(kc + r) * 256 + cs * 8]);
        }
    };

    // prologue: stages 0,1
    stageW(0, 0); stageX(0, 0); CP_COMMIT;
    stageW(1, 1); stageX(1, 1); CP_COMMIT;

    // ---- GEMM1: u = x @ Wu, K=384, 12 chunks, 3-stage pipeline ----
    float acc[NTW][4];
#pragma unroll
    for (int j = 0; j < NTW; j++)
#pragma unroll
        for (int q = 0; q < 4; q++) acc[j][q] = 0.f;

    for (int c = 0; c < 12; c++) {
        if (c == 11) { CP_WAIT0; } else { CP_WAIT1; }
        __syncthreads();
        if (c + 2 < 12) {
            stageW(c + 2, (c + 2) % 3);
            stageX(c + 2, (c + 2) % 3);
            CP_COMMIT;
        }
        const int buf = c % 3;
#pragma unroll
        for (int kk = 0; kk < 2; kk++) {
            uint32_t ah[4];
            LDSM_X4(ah, smaddr(&sXH[buf * XBUF + (wm * 16 + a_row) * 40 + kk * 16 + a_col]));
#pragma unroll
            for (int j = 0; j < NTW; j += 2) {
                const int n0 = nw0 + j * 8;
                if (n0 <= limit) {   // warp-uniform causal tile-pair skip
                    uint32_t bh[4];
                    LDSM_X4_T(bh, smaddr(&sWH[(buf * 32 + kk * 16 + kt_off) * SLIMP + n0 + nt_off]));
                    MMA_F16(acc[j],     ah, bh);
                    MMA_F16(acc[j + 1], ah, bh + 2);
                }
            }
        }
    }
    __syncthreads();   // all reads of phase-1 buffers done before v overlay

    // ---- v staging into dead phase-1 region, overlapped with softmax ----
    for (int L = tid; L < SLIM * 8; L += 256) {
        int s = L >> 3, seg = L & 7;
        CP_ASYNC16(smaddr(&sV[s * 72 + seg * 8]),
                   &g_v[(size_t)(b * NT + s) * 64 + seg * 8]);
    }
    CP_COMMIT;

    // ---- tanh + causal mask + exp + row sums (tanh bounded: no max pass) ----
    const int tg0 = tb * 64 + wm * 16 + qr;
    float rsum0 = 0.f, rsum1 = 0.f;
#pragma unroll
    for (int j = 0; j < NTW; j++) {
        const int c0 = nw0 + j * 8 + qc;
        if (nw0 + j * 8 <= limit) {
            float v0 = (c0     <= tg0    ) ? __expf(tanh_fast(acc[j][0])) : 0.f;
            float v1 = (c0 + 1 <= tg0    ) ? __expf(tanh_fast(acc[j][1])) : 0.f;
            float v2 = (c0     <= tg0 + 8) ? __expf(tanh_fast(acc[j][2])) : 0.f;
            float v3 = (c0 + 1 <= tg0 + 8) ? __expf(tanh_fast(acc[j][3])) : 0.f;
            acc[j][0] = v0; acc[j][1] = v1; acc[j][2] = v2; acc[j][3] = v3;
            rsum0 += v0 + v1;
            rsum1 += v2 + v3;
        }
    }
#pragma unroll
    for (int off = 1; off <= 2; off <<= 1) {
        rsum0 += __shfl_xor_sync(0xffffffffu, rsum0, off);
        rsum1 += __shfl_xor_sync(0xffffffffu, rsum1, off);
    }
    if ((lane & 3) == 0) {
        rowsumS[wn * 64 + wm * 16 + qr]     = rsum0;
        rowsumS[wn * 64 + wm * 16 + qr + 8] = rsum1;
    }
    __syncthreads();
    const float inv0 = 1.f / (rowsumS[wm * 16 + qr]     + rowsumS[64 + wm * 16 + qr]);
    const float inv1 = 1.f / (rowsumS[wm * 16 + qr + 8] + rowsumS[64 + wm * 16 + qr + 8]);

    CP_WAIT0;
    __syncthreads();

    // ---- GEMM2: out += p @ v over k in [wn*KW, wn*KW+KW); p single fp16 ----
    float acc2[8][4];
#pragma unroll
    for (int jo = 0; jo < 8; jo++)
#pragma unroll
        for (int q = 0; q < 4; q++) acc2[jo][q] = 0.f;

#pragma unroll
    for (int jp = 0; jp < NTW / 2; jp++) {
        const int k0 = nw0 + jp * 16;
        if (k0 <= limit) {   // warp-uniform causal k-pair skip
            uint32_t pa_h[4];
            pa_h[0] = pack_h2(acc[2*jp][0]   * inv0, acc[2*jp][1]   * inv0);
            pa_h[1] = pack_h2(acc[2*jp][2]   * inv1, acc[2*jp][3]   * inv1);
            pa_h[2] = pack_h2(acc[2*jp+1][0] * inv0, acc[2*jp+1][1] * inv0);
            pa_h[3] = pack_h2(acc[2*jp+1][2] * inv1, acc[2*jp+1][3] * inv1);

#pragma unroll
            for (int jo = 0; jo < 8; jo += 2) {
                uint32_t bh[4];
                LDSM_X4_T(bh, smaddr(&sV[(k0 + kt_off) * 72 + jo * 8 + nt_off]));
                MMA_F16(acc2[jo],     pa_h, bh);
                MMA_F16(acc2[jo + 1], pa_h, bh + 2);
            }
        }
    }

    // ---- cross-warp k-reduction: both halves store, all threads add+store ----
    __syncthreads();   // v reads done; sOut regions reusable
    {
        float* dst = wn ? sOutB : sOutA;
#pragma unroll
        for (int jo = 0; jo < 8; jo++) {
            *(float2*)&dst[(wm * 16 + qr)     * 72 + jo * 8 + qc] =
                make_float2(acc2[jo][0], acc2[jo][1]);
            *(float2*)&dst[(wm * 16 + qr + 8) * 72 + jo * 8 + qc] =
                make_float2(acc2[jo][2], acc2[jo][3]);
        }
    }
    __syncthreads();
    for (int L = tid; L < 64 * 32; L += 256) {
        int row = L >> 5, c2 = (L & 31) * 2;
        float2 pa = *(float2*)&sOutA[row * 72 + c2];
        float2 pb = *(float2*)&sOutB[row * 72 + c2];
        *(float2*)&out[(size_t)(base_row + row) * NH + c2] =
            make_float2(pa.x + pb.x, pa.y + pb.y);
    }
}

__global__ __launch_bounds__(256, 2) void attn_kernel(float* __restrict__ out)
{
    // heavy-first 1D order: bid 0-511 -> tb=3 (SLIM=256), ..., 1536-2047 -> tb=0
    const int bid = blockIdx.x;
    const int tb  = 3 - (bid >> 9);
    const int b   = bid & 511;
    if (tb == 3)      attn_body<256>(out, b, 3);
    else if (tb == 2) attn_body<192>(out, b, 2);
    else if (tb == 1) attn_body<128>(out, b, 1);
    else              attn_body<64 >(out, b, 0);
}

extern "C" void kernel_launch(void* const* d_in, const int* in_sizes, int n_in,
                              void* d_out, int out_size)
{
    (void)in_sizes; (void)n_in; (void)out_size;
    const float* x   = (const float*)d_in[0];
    const float* Wq  = (const float*)d_in[1];
    const float* Wk  = (const float*)d_in[2];
    const float* Wv  = (const float*)d_in[3];
    const float* Wql = (const float*)d_in[4];
    const float* Wkl = (const float*)d_in[5];
    float* out = (float*)d_out;

    cudaFuncSetAttribute((const void*)attn_kernel,
                         cudaFuncAttributeMaxDynamicSharedMemorySize, ATTN_SMEM_BYTES);
    cudaFuncSetAttribute((const void*)vproj_kernel,
                         cudaFuncAttributeMaxDynamicSharedMemorySize, VPROJ_SMEM);

    prep_kernel<<<480, 256>>>(Wq, Wk, Wql, Wkl, Wv);
    vproj_kernel<<<NM / 256, 256, VPROJ_SMEM>>>(x);

    attn_kernel<<<2048, 256, ATTN_SMEM_BYTES>>>(out);
}